// round 9
// baseline (speedup 1.0000x reference)
#include <cuda_runtime.h>
#include <cuda_bf16.h>
#include <math.h>

// Problem constants (fixed shapes from reference)
#define T_TOK 4096
#define H_DIM 2048
#define I_DIM 8192
#define N_EXP 8
#define TOPK  2

#define MAXROWS 8704     // sum over experts of round64(count) <= 8192 + 8*63 -> 8704
#define MAXBLK  136      // MAXROWS / 64

// ---------------- scratch (static device globals; no allocations) ----------------
__device__ int   g_sel[T_TOK * TOPK];
__device__ float g_wt [T_TOK * TOPK];
__device__ int   g_cnt[N_EXP];
__device__ int   g_off[N_EXP];
__device__ int   g_tok[MAXROWS];
__device__ float g_rwt[MAXROWS];
__device__ int   g_blk_expert[MAXBLK];
__device__ float g_hmid[(size_t)MAXROWS * I_DIM];   // ~285 MB

__device__ __forceinline__ float gelu_exact(float v) {
    return 0.5f * v * (1.0f + erff(v * 0.70710678118654752440f));
}

// ---------------- 1. Router: logits, softmax, top-2, normalized weights ----------------
__global__ void router_kernel(const float* __restrict__ x,
                              const float* __restrict__ gw,
                              float* __restrict__ logits_out) {
    int warp = threadIdx.x >> 5;
    int lane = threadIdx.x & 31;
    int t = blockIdx.x * 8 + warp;
    if (t >= T_TOK) return;
    const float* xr = x + (size_t)t * H_DIM;

    float acc[N_EXP];
#pragma unroll
    for (int e = 0; e < N_EXP; e++) acc[e] = 0.f;

    for (int i = lane; i < H_DIM; i += 32) {
        float xv = xr[i];
        const float* g = gw + (size_t)i * N_EXP;
#pragma unroll
        for (int e = 0; e < N_EXP; e++) acc[e] += xv * g[e];
    }
#pragma unroll
    for (int off = 16; off > 0; off >>= 1) {
#pragma unroll
        for (int e = 0; e < N_EXP; e++)
            acc[e] += __shfl_xor_sync(0xffffffffu, acc[e], off);
    }

    if (lane == 0) {
        // softmax
        float m = acc[0];
#pragma unroll
        for (int e = 1; e < N_EXP; e++) m = fmaxf(m, acc[e]);
        float p[N_EXP];
        float s = 0.f;
#pragma unroll
        for (int e = 0; e < N_EXP; e++) { p[e] = expf(acc[e] - m); s += p[e]; }
        float inv = 1.0f / s;
#pragma unroll
        for (int e = 0; e < N_EXP; e++) p[e] *= inv;

        // top-2 (first occurrence wins ties, matching jax top_k)
        int e1 = 0; float b1 = p[0];
#pragma unroll
        for (int e = 1; e < N_EXP; e++) if (p[e] > b1) { b1 = p[e]; e1 = e; }
        int e2 = -1; float b2 = -1.f;
#pragma unroll
        for (int e = 0; e < N_EXP; e++)
            if (e != e1 && p[e] > b2) { b2 = p[e]; e2 = e; }

        float snorm = b1 + b2;
        g_sel[t * 2 + 0] = e1;
        g_sel[t * 2 + 1] = e2;
        g_wt [t * 2 + 0] = b1 / snorm;
        g_wt [t * 2 + 1] = b2 / snorm;

        if (logits_out) {
#pragma unroll
            for (int e = 0; e < N_EXP; e++) logits_out[(size_t)t * N_EXP + e] = acc[e];
        }
    }
}

// ---------------- 2. Deterministic gather: per-expert token lists (token order) ----------------
__global__ void gather_kernel() {
    const unsigned full = 0xffffffffu;
    int warp = threadIdx.x >> 5;   // warp == expert id (8 warps)
    int lane = threadIdx.x & 31;
    int e = warp;

    // phase 1: count
    int cnt = 0;
    for (int base = 0; base < T_TOK; base += 32) {
        int t = base + lane;
        bool sel = (g_sel[t * 2] == e) || (g_sel[t * 2 + 1] == e);
        unsigned m = __ballot_sync(full, sel);
        cnt += __popc(m);
    }
    if (lane == 0) g_cnt[e] = cnt;
    __syncthreads();

    // offsets + rowblock->expert map (single thread, tiny)
    if (threadIdx.x == 0) {
        int off = 0;
        for (int ee = 0; ee < N_EXP; ee++) {
            g_off[ee] = off;
            int pad = (g_cnt[ee] + 63) & ~63;
            for (int b = 0; b < pad / 64; b++) g_blk_expert[off / 64 + b] = ee;
            off += pad;
        }
        for (int b = off / 64; b < MAXBLK; b++) g_blk_expert[b] = -1;
    }
    __syncthreads();

    // phase 2: compact write in token order
    int pos = g_off[e];
    for (int base = 0; base < T_TOK; base += 32) {
        int t = base + lane;
        int slot = (g_sel[t * 2] == e) ? 0 : ((g_sel[t * 2 + 1] == e) ? 1 : -1);
        unsigned m = __ballot_sync(full, slot >= 0);
        if (slot >= 0) {
            int idx = pos + __popc(m & ((1u << lane) - 1u));
            g_tok[idx] = t;
            g_rwt[idx] = g_wt[t * 2 + slot];
        }
        pos += __popc(m);
    }
    // padding rows
    int c = g_cnt[e];
    int padded = (c + 63) & ~63;
    for (int r = c + lane; r < padded; r += 32) {
        g_tok[g_off[e] + r] = -1;
        g_rwt[g_off[e] + r] = 0.f;
    }
}

// ---------------- 3. GEMM1: hmid = gelu(X_gathered @ w_in[e])  (64x128x16 fp32) ----------------
__global__ void __launch_bounds__(256) gemm1_kernel(const float* __restrict__ x,
                                                    const float* __restrict__ w_in) {
    int e = g_blk_expert[blockIdx.y];
    if (e < 0) return;
    const float* B = w_in + (size_t)e * H_DIM * I_DIM;
    int row0 = blockIdx.y * 64;
    int col0 = blockIdx.x * 128;

    __shared__ float As[16][64];
    __shared__ float Bs[16][132];  // +4 pad

    int tid = threadIdx.x;
    // A load: 64 rows x 16 k, float4 along k
    int ar  = tid & 63;
    int akq = tid >> 6;            // 0..3
    // B load: 16 rows x 128 cols, two float4 per thread along cols
    int bk  = tid >> 4;            // 0..15
    int bc  = (tid & 15) << 2;     // 0..60
    // compute mapping: 4 rows x 8 cols per thread
    int tr = tid >> 4;             // 0..15 -> rows tr*4..tr*4+3
    int tc = tid & 15;             // 0..15 -> cols tc*8..tc*8+7

    int atok = g_tok[row0 + ar];
    const float* aptr = (atok >= 0) ? (x + (size_t)atok * H_DIM + akq * 4) : nullptr;
    const float* bptr = B + (size_t)bk * I_DIM + col0 + bc;

    float acc[4][8];
#pragma unroll
    for (int i = 0; i < 4; i++)
#pragma unroll
        for (int j = 0; j < 8; j++) acc[i][j] = 0.f;

    for (int k0 = 0; k0 < H_DIM; k0 += 16) {
        float4 av = make_float4(0.f, 0.f, 0.f, 0.f);
        if (aptr) av = *(const float4*)(aptr + k0);
        float4 bv0 = *(const float4*)(bptr + (size_t)k0 * I_DIM);
        float4 bv1 = *(const float4*)(bptr + (size_t)k0 * I_DIM + 64);

        As[akq * 4 + 0][ar] = av.x;
        As[akq * 4 + 1][ar] = av.y;
        As[akq * 4 + 2][ar] = av.z;
        As[akq * 4 + 3][ar] = av.w;
        *(float4*)&Bs[bk][bc]      = bv0;
        *(float4*)&Bs[bk][bc + 64] = bv1;
        __syncthreads();

#pragma unroll
        for (int kk = 0; kk < 16; kk++) {
            float4 a  = *(const float4*)&As[kk][tr << 2];
            float4 b0 = *(const float4*)&Bs[kk][tc << 3];
            float4 b1 = *(const float4*)&Bs[kk][(tc << 3) + 4];
            float ai[4] = {a.x, a.y, a.z, a.w};
            float bj[8] = {b0.x, b0.y, b0.z, b0.w, b1.x, b1.y, b1.z, b1.w};
#pragma unroll
            for (int i = 0; i < 4; i++)
#pragma unroll
                for (int j = 0; j < 8; j++) acc[i][j] += ai[i] * bj[j];
        }
        __syncthreads();
    }

    // epilogue: gelu + store to scratch (padded rows store zeros)
#pragma unroll
    for (int i = 0; i < 4; i++) {
        int rr = row0 + (tr << 2) + i;
        float4 o0, o1;
        o0.x = gelu_exact(acc[i][0]); o0.y = gelu_exact(acc[i][1]);
        o0.z = gelu_exact(acc[i][2]); o0.w = gelu_exact(acc[i][3]);
        o1.x = gelu_exact(acc[i][4]); o1.y = gelu_exact(acc[i][5]);
        o1.z = gelu_exact(acc[i][6]); o1.w = gelu_exact(acc[i][7]);
        float* op = g_hmid + (size_t)rr * I_DIM + col0 + (tc << 3);
        *(float4*)(op)     = o0;
        *(float4*)(op + 4) = o1;
    }
}

// ---------------- 4. GEMM2: out += weight * (hmid @ w_out[e])  (64x128x16 fp32) ----------------
__global__ void __launch_bounds__(256) gemm2_kernel(const float* __restrict__ w_out,
                                                    float* __restrict__ out) {
    int e = g_blk_expert[blockIdx.y];
    if (e < 0) return;
    const float* B = w_out + (size_t)e * I_DIM * H_DIM;
    int row0 = blockIdx.y * 64;
    int col0 = blockIdx.x * 128;

    __shared__ float As[16][64];
    __shared__ float Bs[16][132];

    int tid = threadIdx.x;
    int ar  = tid & 63;
    int akq = tid >> 6;
    int bk  = tid >> 4;
    int bc  = (tid & 15) << 2;
    int tr = tid >> 4;
    int tc = tid & 15;

    const float* aptr = g_hmid + (size_t)(row0 + ar) * I_DIM + akq * 4;
    const float* bptr = B + (size_t)bk * H_DIM + col0 + bc;

    float acc[4][8];
#pragma unroll
    for (int i = 0; i < 4; i++)
#pragma unroll
        for (int j = 0; j < 8; j++) acc[i][j] = 0.f;

    for (int k0 = 0; k0 < I_DIM; k0 += 16) {
        float4 av  = *(const float4*)(aptr + k0);
        float4 bv0 = *(const float4*)(bptr + (size_t)k0 * H_DIM);
        float4 bv1 = *(const float4*)(bptr + (size_t)k0 * H_DIM + 64);

        As[akq * 4 + 0][ar] = av.x;
        As[akq * 4 + 1][ar] = av.y;
        As[akq * 4 + 2][ar] = av.z;
        As[akq * 4 + 3][ar] = av.w;
        *(float4*)&Bs[bk][bc]      = bv0;
        *(float4*)&Bs[bk][bc + 64] = bv1;
        __syncthreads();

#pragma unroll
        for (int kk = 0; kk < 16; kk++) {
            float4 a  = *(const float4*)&As[kk][tr << 2];
            float4 b0 = *(const float4*)&Bs[kk][tc << 3];
            float4 b1 = *(const float4*)&Bs[kk][(tc << 3) + 4];
            float ai[4] = {a.x, a.y, a.z, a.w};
            float bj[8] = {b0.x, b0.y, b0.z, b0.w, b1.x, b1.y, b1.z, b1.w};
#pragma unroll
            for (int i = 0; i < 4; i++)
#pragma unroll
                for (int j = 0; j < 8; j++) acc[i][j] += ai[i] * bj[j];
        }
        __syncthreads();
    }

    // epilogue: weighted scatter-add (exactly 2 adds/elem onto zero -> deterministic)
#pragma unroll
    for (int i = 0; i < 4; i++) {
        int r = row0 + (tr << 2) + i;
        int t = g_tok[r];
        if (t < 0) continue;
        float w = g_rwt[r];
        float* op = out + (size_t)t * H_DIM + col0 + (tc << 3);
#pragma unroll
        for (int j = 0; j < 8; j++) atomicAdd(op + j, w * acc[i][j]);
    }
}

// ---------------- 5. bias add ----------------
__global__ void bias_kernel(float* __restrict__ out, const float* __restrict__ bias) {
    size_t idx = (size_t)blockIdx.x * blockDim.x + threadIdx.x;
    if (idx < (size_t)T_TOK * H_DIM) out[idx] += bias[idx & (H_DIM - 1)];
}

// ---------------- launch ----------------
extern "C" void kernel_launch(void* const* d_in, const int* in_sizes, int n_in,
                              void* d_out, int out_size) {
    const float* x     = (const float*)d_in[0];   // [B,S,H]
    const float* gw    = (const float*)d_in[1];   // [H,E]
    const float* w_in  = (const float*)d_in[2];   // [E,H,I]
    const float* w_out = (const float*)d_in[3];   // [E,I,H]
    const float* bias  = (const float*)d_in[4];   // [H]
    float* out = (float*)d_out;

    // zero full output (main out accumulated via atomics; logits overwritten by router)
    cudaMemsetAsync(d_out, 0, (size_t)out_size * sizeof(float), 0);

    // router logits live at the tail of d_out if the harness concatenates outputs
    const int n_out_main = T_TOK * H_DIM;
    const int n_logits   = T_TOK * N_EXP;
    float* logits = (out_size >= n_out_main + n_logits)
                        ? (out + (size_t)out_size - n_logits)
                        : nullptr;

    router_kernel<<<T_TOK / 8, 256>>>(x, gw, logits);
    gather_kernel<<<1, 256>>>();
    gemm1_kernel<<<dim3(I_DIM / 128, MAXBLK), 256>>>(x, w_in);
    gemm2_kernel<<<dim3(H_DIM / 128, MAXBLK), 256>>>(w_out, out);
    bias_kernel<<<(T_TOK * H_DIM + 255) / 256, 256>>>(out, bias);
}

// round 10
// speedup vs baseline: 1.0008x; 1.0008x over previous
#include <cuda_runtime.h>
#include <cuda_bf16.h>
#include <math.h>

// Problem constants (fixed shapes from reference)
#define T_TOK 4096
#define H_DIM 2048
#define I_DIM 8192
#define N_EXP 8
#define TOPK  2

#define MAXROWS 8704     // sum over experts of round64(count) <= 8192 + 8*63 -> 8704
#define MAXBLK  136      // MAXROWS / 64

// ---------------- scratch (static device globals; no allocations) ----------------
__device__ int   g_sel[T_TOK * TOPK];
__device__ float g_wt [T_TOK * TOPK];
__device__ int   g_cnt[N_EXP];
__device__ int   g_off[N_EXP];
__device__ int   g_tok[MAXROWS];
__device__ float g_rwt[MAXROWS];
__device__ int   g_blk_expert[MAXBLK];
__device__ float g_hmid[(size_t)MAXROWS * I_DIM];   // ~285 MB

__device__ __forceinline__ float gelu_exact(float v) {
    return 0.5f * v * (1.0f + erff(v * 0.70710678118654752440f));
}

// ---------------- 1. Router: logits, softmax, top-2, normalized weights ----------------
__global__ void router_kernel(const float* __restrict__ x,
                              const float* __restrict__ gw,
                              float* __restrict__ logits_out) {
    int warp = threadIdx.x >> 5;
    int lane = threadIdx.x & 31;
    int t = blockIdx.x * 8 + warp;
    if (t >= T_TOK) return;
    const float* xr = x + (size_t)t * H_DIM;

    float acc[N_EXP];
#pragma unroll
    for (int e = 0; e < N_EXP; e++) acc[e] = 0.f;

    for (int i = lane; i < H_DIM; i += 32) {
        float xv = xr[i];
        const float* g = gw + (size_t)i * N_EXP;
#pragma unroll
        for (int e = 0; e < N_EXP; e++) acc[e] += xv * g[e];
    }
#pragma unroll
    for (int off = 16; off > 0; off >>= 1) {
#pragma unroll
        for (int e = 0; e < N_EXP; e++)
            acc[e] += __shfl_xor_sync(0xffffffffu, acc[e], off);
    }

    if (lane == 0) {
        // softmax
        float m = acc[0];
#pragma unroll
        for (int e = 1; e < N_EXP; e++) m = fmaxf(m, acc[e]);
        float p[N_EXP];
        float s = 0.f;
#pragma unroll
        for (int e = 0; e < N_EXP; e++) { p[e] = expf(acc[e] - m); s += p[e]; }
        float inv = 1.0f / s;
#pragma unroll
        for (int e = 0; e < N_EXP; e++) p[e] *= inv;

        // top-2 (first occurrence wins ties, matching jax top_k)
        int e1 = 0; float b1 = p[0];
#pragma unroll
        for (int e = 1; e < N_EXP; e++) if (p[e] > b1) { b1 = p[e]; e1 = e; }
        int e2 = -1; float b2 = -1.f;
#pragma unroll
        for (int e = 0; e < N_EXP; e++)
            if (e != e1 && p[e] > b2) { b2 = p[e]; e2 = e; }

        float snorm = b1 + b2;
        g_sel[t * 2 + 0] = e1;
        g_sel[t * 2 + 1] = e2;
        g_wt [t * 2 + 0] = b1 / snorm;
        g_wt [t * 2 + 1] = b2 / snorm;

        if (logits_out) {
#pragma unroll
            for (int e = 0; e < N_EXP; e++) logits_out[(size_t)t * N_EXP + e] = acc[e];
        }
    }
}

// ---------------- 2. Deterministic gather: per-expert token lists (token order) ----------------
__global__ void gather_kernel() {
    const unsigned full = 0xffffffffu;
    int warp = threadIdx.x >> 5;   // warp == expert id (8 warps)
    int lane = threadIdx.x & 31;
    int e = warp;

    // phase 1: count
    int cnt = 0;
    for (int base = 0; base < T_TOK; base += 32) {
        int t = base + lane;
        bool sel = (g_sel[t * 2] == e) || (g_sel[t * 2 + 1] == e);
        unsigned m = __ballot_sync(full, sel);
        cnt += __popc(m);
    }
    if (lane == 0) g_cnt[e] = cnt;
    __syncthreads();

    // offsets + rowblock->expert map (single thread, tiny)
    if (threadIdx.x == 0) {
        int off = 0;
        for (int ee = 0; ee < N_EXP; ee++) {
            g_off[ee] = off;
            int pad = (g_cnt[ee] + 63) & ~63;
            for (int b = 0; b < pad / 64; b++) g_blk_expert[off / 64 + b] = ee;
            off += pad;
        }
        for (int b = off / 64; b < MAXBLK; b++) g_blk_expert[b] = -1;
    }
    __syncthreads();

    // phase 2: compact write in token order
    int pos = g_off[e];
    for (int base = 0; base < T_TOK; base += 32) {
        int t = base + lane;
        int slot = (g_sel[t * 2] == e) ? 0 : ((g_sel[t * 2 + 1] == e) ? 1 : -1);
        unsigned m = __ballot_sync(full, slot >= 0);
        if (slot >= 0) {
            int idx = pos + __popc(m & ((1u << lane) - 1u));
            g_tok[idx] = t;
            g_rwt[idx] = g_wt[t * 2 + slot];
        }
        pos += __popc(m);
    }
    // padding rows
    int c = g_cnt[e];
    int padded = (c + 63) & ~63;
    for (int r = c + lane; r < padded; r += 32) {
        g_tok[g_off[e] + r] = -1;
        g_rwt[g_off[e] + r] = 0.f;
    }
}

// ---------------- 3. GEMM1: hmid = gelu(X_gathered @ w_in[e])  (64x128x16 fp32) ----------------
__global__ void __launch_bounds__(256) gemm1_kernel(const float* __restrict__ x,
                                                    const float* __restrict__ w_in) {
    int e = g_blk_expert[blockIdx.y];
    if (e < 0) return;
    const float* B = w_in + (size_t)e * H_DIM * I_DIM;
    int row0 = blockIdx.y * 64;
    int col0 = blockIdx.x * 128;

    __shared__ float As[16][64];
    __shared__ float Bs[16][132];  // +4 pad

    int tid = threadIdx.x;
    // A load: 64 rows x 16 k, float4 along k
    int ar  = tid & 63;
    int akq = tid >> 6;            // 0..3
    // B load: 16 rows x 128 cols, two float4 per thread along cols
    int bk  = tid >> 4;            // 0..15
    int bc  = (tid & 15) << 2;     // 0..60
    // compute mapping: 4 rows x 8 cols per thread
    int tr = tid >> 4;             // 0..15 -> rows tr*4..tr*4+3
    int tc = tid & 15;             // 0..15 -> cols tc*8..tc*8+7

    int atok = g_tok[row0 + ar];
    const float* aptr = (atok >= 0) ? (x + (size_t)atok * H_DIM + akq * 4) : nullptr;
    const float* bptr = B + (size_t)bk * I_DIM + col0 + bc;

    float acc[4][8];
#pragma unroll
    for (int i = 0; i < 4; i++)
#pragma unroll
        for (int j = 0; j < 8; j++) acc[i][j] = 0.f;

    for (int k0 = 0; k0 < H_DIM; k0 += 16) {
        float4 av = make_float4(0.f, 0.f, 0.f, 0.f);
        if (aptr) av = *(const float4*)(aptr + k0);
        float4 bv0 = *(const float4*)(bptr + (size_t)k0 * I_DIM);
        float4 bv1 = *(const float4*)(bptr + (size_t)k0 * I_DIM + 64);

        As[akq * 4 + 0][ar] = av.x;
        As[akq * 4 + 1][ar] = av.y;
        As[akq * 4 + 2][ar] = av.z;
        As[akq * 4 + 3][ar] = av.w;
        *(float4*)&Bs[bk][bc]      = bv0;
        *(float4*)&Bs[bk][bc + 64] = bv1;
        __syncthreads();

#pragma unroll
        for (int kk = 0; kk < 16; kk++) {
            float4 a  = *(const float4*)&As[kk][tr << 2];
            float4 b0 = *(const float4*)&Bs[kk][tc << 3];
            float4 b1 = *(const float4*)&Bs[kk][(tc << 3) + 4];
            float ai[4] = {a.x, a.y, a.z, a.w};
            float bj[8] = {b0.x, b0.y, b0.z, b0.w, b1.x, b1.y, b1.z, b1.w};
#pragma unroll
            for (int i = 0; i < 4; i++)
#pragma unroll
                for (int j = 0; j < 8; j++) acc[i][j] += ai[i] * bj[j];
        }
        __syncthreads();
    }

    // epilogue: gelu + store to scratch (padded rows store zeros)
#pragma unroll
    for (int i = 0; i < 4; i++) {
        int rr = row0 + (tr << 2) + i;
        float4 o0, o1;
        o0.x = gelu_exact(acc[i][0]); o0.y = gelu_exact(acc[i][1]);
        o0.z = gelu_exact(acc[i][2]); o0.w = gelu_exact(acc[i][3]);
        o1.x = gelu_exact(acc[i][4]); o1.y = gelu_exact(acc[i][5]);
        o1.z = gelu_exact(acc[i][6]); o1.w = gelu_exact(acc[i][7]);
        float* op = g_hmid + (size_t)rr * I_DIM + col0 + (tc << 3);
        *(float4*)(op)     = o0;
        *(float4*)(op + 4) = o1;
    }
}

// ---------------- 4. GEMM2: out += weight * (hmid @ w_out[e])  (64x128x16 fp32) ----------------
__global__ void __launch_bounds__(256) gemm2_kernel(const float* __restrict__ w_out,
                                                    float* __restrict__ out) {
    int e = g_blk_expert[blockIdx.y];
    if (e < 0) return;
    const float* B = w_out + (size_t)e * I_DIM * H_DIM;
    int row0 = blockIdx.y * 64;
    int col0 = blockIdx.x * 128;

    __shared__ float As[16][64];
    __shared__ float Bs[16][132];

    int tid = threadIdx.x;
    int ar  = tid & 63;
    int akq = tid >> 6;
    int bk  = tid >> 4;
    int bc  = (tid & 15) << 2;
    int tr = tid >> 4;
    int tc = tid & 15;

    const float* aptr = g_hmid + (size_t)(row0 + ar) * I_DIM + akq * 4;
    const float* bptr = B + (size_t)bk * H_DIM + col0 + bc;

    float acc[4][8];
#pragma unroll
    for (int i = 0; i < 4; i++)
#pragma unroll
        for (int j = 0; j < 8; j++) acc[i][j] = 0.f;

    for (int k0 = 0; k0 < I_DIM; k0 += 16) {
        float4 av  = *(const float4*)(aptr + k0);
        float4 bv0 = *(const float4*)(bptr + (size_t)k0 * H_DIM);
        float4 bv1 = *(const float4*)(bptr + (size_t)k0 * H_DIM + 64);

        As[akq * 4 + 0][ar] = av.x;
        As[akq * 4 + 1][ar] = av.y;
        As[akq * 4 + 2][ar] = av.z;
        As[akq * 4 + 3][ar] = av.w;
        *(float4*)&Bs[bk][bc]      = bv0;
        *(float4*)&Bs[bk][bc + 64] = bv1;
        __syncthreads();

#pragma unroll
        for (int kk = 0; kk < 16; kk++) {
            float4 a  = *(const float4*)&As[kk][tr << 2];
            float4 b0 = *(const float4*)&Bs[kk][tc << 3];
            float4 b1 = *(const float4*)&Bs[kk][(tc << 3) + 4];
            float ai[4] = {a.x, a.y, a.z, a.w};
            float bj[8] = {b0.x, b0.y, b0.z, b0.w, b1.x, b1.y, b1.z, b1.w};
#pragma unroll
            for (int i = 0; i < 4; i++)
#pragma unroll
                for (int j = 0; j < 8; j++) acc[i][j] += ai[i] * bj[j];
        }
        __syncthreads();
    }

    // epilogue: weighted scatter-add (exactly 2 adds/elem onto zero -> deterministic)
#pragma unroll
    for (int i = 0; i < 4; i++) {
        int r = row0 + (tr << 2) + i;
        int t = g_tok[r];
        if (t < 0) continue;
        float w = g_rwt[r];
        float* op = out + (size_t)t * H_DIM + col0 + (tc << 3);
#pragma unroll
        for (int j = 0; j < 8; j++) atomicAdd(op + j, w * acc[i][j]);
    }
}

// ---------------- 5. bias add ----------------
__global__ void bias_kernel(float* __restrict__ out, const float* __restrict__ bias) {
    size_t idx = (size_t)blockIdx.x * blockDim.x + threadIdx.x;
    if (idx < (size_t)T_TOK * H_DIM) out[idx] += bias[idx & (H_DIM - 1)];
}

// ---------------- launch ----------------
extern "C" void kernel_launch(void* const* d_in, const int* in_sizes, int n_in,
                              void* d_out, int out_size) {
    const float* x     = (const float*)d_in[0];   // [B,S,H]
    const float* gw    = (const float*)d_in[1];   // [H,E]
    const float* w_in  = (const float*)d_in[2];   // [E,H,I]
    const float* w_out = (const float*)d_in[3];   // [E,I,H]
    const float* bias  = (const float*)d_in[4];   // [H]
    float* out = (float*)d_out;

    // zero full output (main out accumulated via atomics; logits overwritten by router)
    cudaMemsetAsync(d_out, 0, (size_t)out_size * sizeof(float), 0);

    // router logits live at the tail of d_out if the harness concatenates outputs
    const int n_out_main = T_TOK * H_DIM;
    const int n_logits   = T_TOK * N_EXP;
    float* logits = (out_size >= n_out_main + n_logits)
                        ? (out + (size_t)out_size - n_logits)
                        : nullptr;

    router_kernel<<<T_TOK / 8, 256>>>(x, gw, logits);
    gather_kernel<<<1, 256>>>();
    gemm1_kernel<<<dim3(I_DIM / 128, MAXBLK), 256>>>(x, w_in);
    gemm2_kernel<<<dim3(H_DIM / 128, MAXBLK), 256>>>(w_out, out);
    bias_kernel<<<(T_TOK * H_DIM + 255) / 256, 256>>>(out, bias);
}

// round 13
// speedup vs baseline: 2.7715x; 2.7694x over previous
#include <cuda_runtime.h>
#include <cuda_bf16.h>
#include <math.h>
#include <stdint.h>

// Problem constants
#define T_TOK 4096
#define H_DIM 2048
#define I_DIM 8192
#define N_EXP 8
#define TOPK  2

#define MTILE   128
#define NTILE   128
#define KCHUNK  32
#define STAGES  3
#define MAXROWS 9216     // 8192 + 8*127 rounded up to 128
#define MAXBLK  72       // MAXROWS / 128

// per-stage smem layout (bytes): Ah | Al | Bh | Bl, each 128 rows x 80B (32 bf16 + 16B pad)
#define ROWB      80
#define MATB      (128 * ROWB)     // 10240
#define STAGEB    (4 * MATB)       // 40960
#define DSMEM     (STAGES * STAGEB)

// ---------------- scratch (static device globals; no allocations) ----------------
__device__ int   g_sel[T_TOK * TOPK];
__device__ float g_wt [T_TOK * TOPK];
__device__ int   g_cnt[N_EXP];
__device__ int   g_off[N_EXP];
__device__ int   g_total;
__device__ int   g_tok[MAXROWS];
__device__ float g_rwt[MAXROWS];
__device__ int   g_blk_expert[MAXBLK];

// bf16 split operands
__device__ __nv_bfloat16 g_a_hi[(size_t)MAXROWS * H_DIM];
__device__ __nv_bfloat16 g_a_lo[(size_t)MAXROWS * H_DIM];
__device__ __nv_bfloat16 g_h_hi[(size_t)MAXROWS * I_DIM];
__device__ __nv_bfloat16 g_h_lo[(size_t)MAXROWS * I_DIM];
__device__ __nv_bfloat16 g_w1h[(size_t)N_EXP * I_DIM * H_DIM];  // w_in^T  [E][I][H]
__device__ __nv_bfloat16 g_w1l[(size_t)N_EXP * I_DIM * H_DIM];
__device__ __nv_bfloat16 g_w2h[(size_t)N_EXP * H_DIM * I_DIM];  // w_out^T [E][H][I]
__device__ __nv_bfloat16 g_w2l[(size_t)N_EXP * H_DIM * I_DIM];

__device__ __forceinline__ float gelu_exact(float v) {
    return 0.5f * v * (1.0f + erff(v * 0.70710678118654752440f));
}

__device__ __forceinline__ uint32_t smem_u32(const void* p) {
    uint32_t a;
    asm("{ .reg .u64 t; cvta.to.shared.u64 t, %1; cvt.u32.u64 %0, t; }" : "=r"(a) : "l"(p));
    return a;
}

// ---------------- family-portable PTX: cp.async / ldmatrix / mma.sync ----------------
#define CP_ASYNC16(sm, gp) \
    asm volatile("cp.async.cg.shared.global [%0], [%1], 16;" :: "r"(sm), "l"(gp))
#define CP_COMMIT() asm volatile("cp.async.commit_group;" ::: "memory")
#define CP_WAIT(n)  asm volatile("cp.async.wait_group %0;" :: "n"(n) : "memory")

#define LDSM4(r, addr) \
    asm volatile("ldmatrix.sync.aligned.m8n8.x4.shared.b16 {%0,%1,%2,%3}, [%4];" \
        : "=r"((r)[0]), "=r"((r)[1]), "=r"((r)[2]), "=r"((r)[3]) : "r"(addr))

__device__ __forceinline__ void mma_bf16(float* d, const uint32_t* a, const uint32_t* b) {
    asm volatile(
        "mma.sync.aligned.m16n8k16.row.col.f32.bf16.bf16.f32 "
        "{%0,%1,%2,%3}, {%4,%5,%6,%7}, {%8,%9}, {%0,%1,%2,%3};"
        : "+f"(d[0]), "+f"(d[1]), "+f"(d[2]), "+f"(d[3])
        : "r"(a[0]), "r"(a[1]), "r"(a[2]), "r"(a[3]), "r"(b[0]), "r"(b[1]));
}

// ---------------- 1. Router ----------------
__global__ void router_kernel(const float* __restrict__ x,
                              const float* __restrict__ gw,
                              float* __restrict__ logits_out) {
    int warp = threadIdx.x >> 5;
    int lane = threadIdx.x & 31;
    int t = blockIdx.x * 8 + warp;
    if (t >= T_TOK) return;
    const float* xr = x + (size_t)t * H_DIM;

    float acc[N_EXP];
#pragma unroll
    for (int e = 0; e < N_EXP; e++) acc[e] = 0.f;
    for (int i = lane; i < H_DIM; i += 32) {
        float xv = xr[i];
        const float* g = gw + (size_t)i * N_EXP;
#pragma unroll
        for (int e = 0; e < N_EXP; e++) acc[e] += xv * g[e];
    }
#pragma unroll
    for (int off = 16; off > 0; off >>= 1)
#pragma unroll
        for (int e = 0; e < N_EXP; e++) acc[e] += __shfl_xor_sync(0xffffffffu, acc[e], off);

    if (lane == 0) {
        float m = acc[0];
#pragma unroll
        for (int e = 1; e < N_EXP; e++) m = fmaxf(m, acc[e]);
        float p[N_EXP]; float s = 0.f;
#pragma unroll
        for (int e = 0; e < N_EXP; e++) { p[e] = expf(acc[e] - m); s += p[e]; }
        float inv = 1.0f / s;
#pragma unroll
        for (int e = 0; e < N_EXP; e++) p[e] *= inv;

        int e1 = 0; float b1 = p[0];
#pragma unroll
        for (int e = 1; e < N_EXP; e++) if (p[e] > b1) { b1 = p[e]; e1 = e; }
        int e2 = -1; float b2 = -1.f;
#pragma unroll
        for (int e = 0; e < N_EXP; e++) if (e != e1 && p[e] > b2) { b2 = p[e]; e2 = e; }

        float snorm = b1 + b2;
        g_sel[t * 2 + 0] = e1; g_sel[t * 2 + 1] = e2;
        g_wt [t * 2 + 0] = b1 / snorm; g_wt [t * 2 + 1] = b2 / snorm;
        if (logits_out) {
#pragma unroll
            for (int e = 0; e < N_EXP; e++) logits_out[(size_t)t * N_EXP + e] = acc[e];
        }
    }
}

// ---------------- 2. Gather (pad to 128-row blocks) ----------------
__global__ void gather_kernel() {
    const unsigned full = 0xffffffffu;
    int warp = threadIdx.x >> 5;
    int lane = threadIdx.x & 31;
    int e = warp;

    int cnt = 0;
    for (int base = 0; base < T_TOK; base += 32) {
        int t = base + lane;
        bool sel = (g_sel[t * 2] == e) || (g_sel[t * 2 + 1] == e);
        unsigned m = __ballot_sync(full, sel);
        cnt += __popc(m);
    }
    if (lane == 0) g_cnt[e] = cnt;
    __syncthreads();

    if (threadIdx.x == 0) {
        int off = 0;
        for (int ee = 0; ee < N_EXP; ee++) {
            g_off[ee] = off;
            int pad = (g_cnt[ee] + 127) & ~127;
            for (int b = 0; b < pad / 128; b++) g_blk_expert[off / 128 + b] = ee;
            off += pad;
        }
        for (int b = off / 128; b < MAXBLK; b++) g_blk_expert[b] = -1;
        g_total = off;
    }
    __syncthreads();

    int pos = g_off[e];
    for (int base = 0; base < T_TOK; base += 32) {
        int t = base + lane;
        int slot = (g_sel[t * 2] == e) ? 0 : ((g_sel[t * 2 + 1] == e) ? 1 : -1);
        unsigned m = __ballot_sync(full, slot >= 0);
        if (slot >= 0) {
            int idx = pos + __popc(m & ((1u << lane) - 1u));
            g_tok[idx] = t;
            g_rwt[idx] = g_wt[t * 2 + slot];
        }
        pos += __popc(m);
    }
    int c = g_cnt[e];
    int padded = (c + 127) & ~127;
    for (int r = c + lane; r < padded; r += 32) {
        g_tok[g_off[e] + r] = -1;
        g_rwt[g_off[e] + r] = 0.f;
    }
    __syncthreads();
    for (int i = g_total + threadIdx.x; i < MAXROWS; i += 256) { g_tok[i] = -1; g_rwt[i] = 0.f; }
}

// ---------------- 3. Convert gathered x -> bf16 hi/lo ----------------
__device__ __forceinline__ void split2(float a, float b, uint32_t& h, uint32_t& l) {
    __nv_bfloat16 ha = __float2bfloat16(a), hb = __float2bfloat16(b);
    float ra = a - __bfloat162float(ha), rb = b - __bfloat162float(hb);
    __nv_bfloat16 la = __float2bfloat16(ra), lb = __float2bfloat16(rb);
    h = (uint32_t)__bfloat16_as_ushort(ha) | ((uint32_t)__bfloat16_as_ushort(hb) << 16);
    l = (uint32_t)__bfloat16_as_ushort(la) | ((uint32_t)__bfloat16_as_ushort(lb) << 16);
}

__global__ void conv_x_kernel(const float* __restrict__ x) {
    int row = blockIdx.x;
    int t = g_tok[row];
    const float4* src = (t >= 0) ? (const float4*)(x + (size_t)t * H_DIM) : nullptr;
    uint2* dh = (uint2*)(g_a_hi + (size_t)row * H_DIM);
    uint2* dl = (uint2*)(g_a_lo + (size_t)row * H_DIM);
    for (int i = threadIdx.x; i < H_DIM / 4; i += 256) {
        float4 v = src ? src[i] : make_float4(0.f, 0.f, 0.f, 0.f);
        uint2 h, l;
        split2(v.x, v.y, h.x, l.x);
        split2(v.z, v.w, h.y, l.y);
        dh[i] = h; dl[i] = l;
    }
}

// ---------------- 4. Weight transpose + convert: [E][R][C] f32 -> [E][C][R] bf16 hi/lo ----------
template<bool W1>
__global__ void conv_w_kernel(const float* __restrict__ src, int R, int C) {
    __shared__ float tile[32][33];
    int e = blockIdx.z;
    const float* s = src + (size_t)e * R * C;
    __nv_bfloat16* ph = (W1 ? g_w1h : g_w2h) + (size_t)e * R * C;
    __nv_bfloat16* pl = (W1 ? g_w1l : g_w2l) + (size_t)e * R * C;
    int c0 = blockIdx.x * 32, r0 = blockIdx.y * 32;
    int tx = threadIdx.x, ty = threadIdx.y;   // (32, 8)
#pragma unroll
    for (int j = 0; j < 4; j++)
        tile[ty * 4 + j][tx] = s[(size_t)(r0 + ty * 4 + j) * C + c0 + tx];
    __syncthreads();
#pragma unroll
    for (int j = 0; j < 4; j++) {
        float v = tile[tx][ty * 4 + j];
        __nv_bfloat16 h = __float2bfloat16(v);
        __nv_bfloat16 l = __float2bfloat16(v - __bfloat162float(h));
        size_t o = (size_t)(c0 + ty * 4 + j) * R + r0 + tx;
        ph[o] = h; pl[o] = l;
    }
}

// ---------------- 5. split-bf16 GEMM via mma.sync (128x128x32, 3-stage cp.async) ----------------
// G1: D = gelu(A @ w_in^T)  -> g_h_hi/lo ;  !G1: out += rwt * (A @ w_out^T)  (atomic scatter)
template<bool G1>
__global__ void __launch_bounds__(256) gemm_mma(float* __restrict__ outp) {
    constexpr int K    = G1 ? H_DIM : I_DIM;
    constexpr int NTOT = G1 ? I_DIM : H_DIM;
    constexpr int NCH  = K / KCHUNK;

    int e = g_blk_expert[blockIdx.y];
    if (e < 0) return;
    int row0 = blockIdx.y * MTILE;
    int col0 = blockIdx.x * NTILE;

    const __nv_bfloat16* srcs[4];
    srcs[0] = (G1 ? g_a_hi : g_h_hi) + (size_t)row0 * K;
    srcs[1] = (G1 ? g_a_lo : g_h_lo) + (size_t)row0 * K;
    srcs[2] = (G1 ? g_w1h : g_w2h) + ((size_t)e * NTOT + col0) * K;
    srcs[3] = (G1 ? g_w1l : g_w2l) + ((size_t)e * NTOT + col0) * K;

    extern __shared__ char dsm[];
    uint32_t sb0 = smem_u32(dsm);

    int tid  = threadIdx.x;
    int wid  = tid >> 5;
    int lane = tid & 31;
    int warpM = wid >> 2;        // 0..1 -> rows 64*warpM
    int warpN = wid & 3;         // 0..3 -> cols 32*warpN

    float acc[4][4][4];
#pragma unroll
    for (int i = 0; i < 4; i++)
#pragma unroll
        for (int j = 0; j < 4; j++)
#pragma unroll
            for (int q = 0; q < 4; q++) acc[i][j][q] = 0.f;

    // ---- cp.async stage loader: 2048 x 16B per stage, 8 per thread ----
    auto load_stage = [&](int stg, int c) {
        uint32_t sb = sb0 + (uint32_t)stg * STAGEB;
        int k0 = c * KCHUNK;
#pragma unroll
        for (int mat = 0; mat < 4; mat++) {
            const __nv_bfloat16* sp = srcs[mat];
#pragma unroll
            for (int j = 0; j < 2; j++) {
                int id = j * 256 + tid;        // 0..511
                int row = id >> 2, c16 = id & 3;
                uint32_t so = sb + mat * MATB + row * ROWB + c16 * 16;
                const void* gp = sp + (size_t)row * K + k0 + c16 * 8;
                CP_ASYNC16(so, gp);
            }
        }
        CP_COMMIT();
    };

    // preload
#pragma unroll
    for (int s = 0; s < STAGES - 1; s++) load_stage(s, s);

    int lr = lane & 15;
    for (int c = 0; c < NCH; c++) {
        if (c + STAGES - 1 < NCH) load_stage((c + STAGES - 1) % STAGES, c + STAGES - 1);
        else CP_COMMIT();                 // keep group count uniform
        CP_WAIT(STAGES - 1);              // stage c resident
        __syncthreads();

        uint32_t sb = sb0 + (uint32_t)(c % STAGES) * STAGEB;
#pragma unroll
        for (int ks = 0; ks < 2; ks++) {
            uint32_t kofs = (uint32_t)(ks * 32 + (lane >> 4) * 16);
            uint32_t ah[4][4], al[4][4], bh[4][2], bl[4][2];
#pragma unroll
            for (int mi = 0; mi < 4; mi++) {
                uint32_t ra = sb + (uint32_t)((warpM * 64 + mi * 16 + lr) * ROWB) + kofs;
                LDSM4(ah[mi], ra);
                LDSM4(al[mi], ra + MATB);
            }
#pragma unroll
            for (int nb = 0; nb < 2; nb++) {
                uint32_t rb = sb + 2u * MATB + (uint32_t)((warpN * 32 + nb * 16 + lr) * ROWB) + kofs;
                uint32_t t0[4], t1[4];
                LDSM4(t0, rb);
                LDSM4(t1, rb + MATB);
                bh[nb * 2][0] = t0[0]; bh[nb * 2][1] = t0[2];
                bh[nb * 2 + 1][0] = t0[1]; bh[nb * 2 + 1][1] = t0[3];
                bl[nb * 2][0] = t1[0]; bl[nb * 2][1] = t1[2];
                bl[nb * 2 + 1][0] = t1[1]; bl[nb * 2 + 1][1] = t1[3];
            }
#pragma unroll
            for (int mi = 0; mi < 4; mi++)
#pragma unroll
                for (int ni = 0; ni < 4; ni++) {
                    mma_bf16(acc[mi][ni], ah[mi], bh[ni]);
                    mma_bf16(acc[mi][ni], ah[mi], bl[ni]);
                    mma_bf16(acc[mi][ni], al[mi], bh[ni]);
                }
        }
        __syncthreads();
    }

    // ---- epilogue ----
    int r = lane >> 2;
    int cp = (lane & 3) * 2;
    if (G1) {
#pragma unroll
        for (int mi = 0; mi < 4; mi++)
#pragma unroll
            for (int ni = 0; ni < 4; ni++) {
                int row = row0 + warpM * 64 + mi * 16 + r;
                int col = col0 + warpN * 32 + ni * 8 + cp;
                float* d = acc[mi][ni];
                uint32_t h0, l0, h1, l1;
                split2(gelu_exact(d[0]), gelu_exact(d[1]), h0, l0);
                split2(gelu_exact(d[2]), gelu_exact(d[3]), h1, l1);
                *(uint32_t*)(g_h_hi + (size_t)row * I_DIM + col) = h0;
                *(uint32_t*)(g_h_lo + (size_t)row * I_DIM + col) = l0;
                *(uint32_t*)(g_h_hi + (size_t)(row + 8) * I_DIM + col) = h1;
                *(uint32_t*)(g_h_lo + (size_t)(row + 8) * I_DIM + col) = l1;
            }
    } else {
#pragma unroll
        for (int mi = 0; mi < 4; mi++) {
            int row = row0 + warpM * 64 + mi * 16 + r;
            int t0 = g_tok[row];
            int t1 = g_tok[row + 8];
            float w0 = g_rwt[row], w1 = g_rwt[row + 8];
#pragma unroll
            for (int ni = 0; ni < 4; ni++) {
                int col = col0 + warpN * 32 + ni * 8 + cp;
                float* d = acc[mi][ni];
                if (t0 >= 0) {
                    float* op = outp + (size_t)t0 * H_DIM + col;
                    atomicAdd(op,     w0 * d[0]);
                    atomicAdd(op + 1, w0 * d[1]);
                }
                if (t1 >= 0) {
                    float* op = outp + (size_t)t1 * H_DIM + col;
                    atomicAdd(op,     w1 * d[2]);
                    atomicAdd(op + 1, w1 * d[3]);
                }
            }
        }
    }
}

// ---------------- 6. bias add ----------------
__global__ void bias_kernel(float* __restrict__ out, const float* __restrict__ bias) {
    size_t idx = (size_t)blockIdx.x * blockDim.x + threadIdx.x;
    if (idx < (size_t)T_TOK * H_DIM) out[idx] += bias[idx & (H_DIM - 1)];
}

// ---------------- launch ----------------
extern "C" void kernel_launch(void* const* d_in, const int* in_sizes, int n_in,
                              void* d_out, int out_size) {
    const float* x     = (const float*)d_in[0];   // [B,S,H]
    const float* gw    = (const float*)d_in[1];   // [H,E]
    const float* w_in  = (const float*)d_in[2];   // [E,H,I]
    const float* w_out = (const float*)d_in[3];   // [E,I,H]
    const float* bias  = (const float*)d_in[4];   // [H]
    float* out = (float*)d_out;

    cudaFuncSetAttribute((const void*)gemm_mma<true>,
                         cudaFuncAttributeMaxDynamicSharedMemorySize, DSMEM);
    cudaFuncSetAttribute((const void*)gemm_mma<false>,
                         cudaFuncAttributeMaxDynamicSharedMemorySize, DSMEM);

    cudaMemsetAsync(d_out, 0, (size_t)out_size * sizeof(float), 0);

    const int n_out_main = T_TOK * H_DIM;
    const int n_logits   = T_TOK * N_EXP;
    float* logits = (out_size >= n_out_main + n_logits)
                        ? (out + (size_t)out_size - n_logits) : nullptr;

    router_kernel<<<T_TOK / 8, 256>>>(x, gw, logits);
    gather_kernel<<<1, 256>>>();
    conv_x_kernel<<<MAXROWS, 256>>>(x);
    conv_w_kernel<true ><<<dim3(I_DIM / 32, H_DIM / 32, N_EXP), dim3(32, 8)>>>(w_in,  H_DIM, I_DIM);
    conv_w_kernel<false><<<dim3(H_DIM / 32, I_DIM / 32, N_EXP), dim3(32, 8)>>>(w_out, I_DIM, H_DIM);
    gemm_mma<true ><<<dim3(I_DIM / NTILE, MAXBLK), 256, DSMEM>>>(nullptr);
    gemm_mma<false><<<dim3(H_DIM / NTILE, MAXBLK), 256, DSMEM>>>(out);
    bias_kernel<<<(T_TOK * H_DIM + 255) / 256, 256>>>(out, bias);
}

// round 14
// speedup vs baseline: 3.0568x; 1.1029x over previous
#include <cuda_runtime.h>
#include <cuda_bf16.h>
#include <math.h>
#include <stdint.h>

// Problem constants
#define T_TOK 4096
#define H_DIM 2048
#define I_DIM 8192
#define N_EXP 8
#define TOPK  2

#define MTILE   128
#define NTILE   256
#define KCHUNK  32
#define STAGES  3
#define MAXROWS 9216     // 8192 + 8*127 rounded up to 128
#define MAXBLK  72       // MAXROWS / 128

// per-stage smem layout (bytes): Ah | Al | Bh | Bl ; rows are 80B (32 bf16 = 64B + 16B pad)
#define ROWB    80
#define AMATB   (128 * ROWB)       // 10240
#define BMATB   (256 * ROWB)       // 20480
#define BBASE   (2 * AMATB)        // 20480
#define STAGEB  (2 * AMATB + 2 * BMATB)   // 61440
#define DSMEM   (STAGES * STAGEB)         // 184320

// ---------------- scratch (static device globals; no allocations) ----------------
__device__ int   g_sel[T_TOK * TOPK];
__device__ float g_wt [T_TOK * TOPK];
__device__ int   g_cnt[N_EXP];
__device__ int   g_off[N_EXP];
__device__ int   g_total;
__device__ int   g_tok[MAXROWS];
__device__ float g_rwt[MAXROWS];
__device__ int   g_blk_expert[MAXBLK];

// bf16 split operands
__device__ __nv_bfloat16 g_a_hi[(size_t)MAXROWS * H_DIM];
__device__ __nv_bfloat16 g_a_lo[(size_t)MAXROWS * H_DIM];
__device__ __nv_bfloat16 g_h_hi[(size_t)MAXROWS * I_DIM];
__device__ __nv_bfloat16 g_h_lo[(size_t)MAXROWS * I_DIM];
__device__ __nv_bfloat16 g_w1h[(size_t)N_EXP * I_DIM * H_DIM];  // w_in^T  [E][I][H]
__device__ __nv_bfloat16 g_w1l[(size_t)N_EXP * I_DIM * H_DIM];
__device__ __nv_bfloat16 g_w2h[(size_t)N_EXP * H_DIM * I_DIM];  // w_out^T [E][H][I]
__device__ __nv_bfloat16 g_w2l[(size_t)N_EXP * H_DIM * I_DIM];

__device__ __forceinline__ float gelu_exact(float v) {
    return 0.5f * v * (1.0f + erff(v * 0.70710678118654752440f));
}

__device__ __forceinline__ uint32_t smem_u32(const void* p) {
    uint32_t a;
    asm("{ .reg .u64 t; cvta.to.shared.u64 t, %1; cvt.u32.u64 %0, t; }" : "=r"(a) : "l"(p));
    return a;
}

// ---------------- family-portable PTX: cp.async / ldmatrix / mma.sync ----------------
#define CP_ASYNC16(sm, gp) \
    asm volatile("cp.async.cg.shared.global [%0], [%1], 16;" :: "r"(sm), "l"(gp))
#define CP_COMMIT() asm volatile("cp.async.commit_group;" ::: "memory")
#define CP_WAIT(n)  asm volatile("cp.async.wait_group %0;" :: "n"(n) : "memory")

#define LDSM4(r, addr) \
    asm volatile("ldmatrix.sync.aligned.m8n8.x4.shared.b16 {%0,%1,%2,%3}, [%4];" \
        : "=r"((r)[0]), "=r"((r)[1]), "=r"((r)[2]), "=r"((r)[3]) : "r"(addr))

__device__ __forceinline__ void mma_bf16(float* d, const uint32_t* a, const uint32_t* b) {
    asm volatile(
        "mma.sync.aligned.m16n8k16.row.col.f32.bf16.bf16.f32 "
        "{%0,%1,%2,%3}, {%4,%5,%6,%7}, {%8,%9}, {%0,%1,%2,%3};"
        : "+f"(d[0]), "+f"(d[1]), "+f"(d[2]), "+f"(d[3])
        : "r"(a[0]), "r"(a[1]), "r"(a[2]), "r"(a[3]), "r"(b[0]), "r"(b[1]));
}

// ---------------- 1. Router ----------------
__global__ void router_kernel(const float* __restrict__ x,
                              const float* __restrict__ gw,
                              float* __restrict__ logits_out) {
    int warp = threadIdx.x >> 5;
    int lane = threadIdx.x & 31;
    int t = blockIdx.x * 8 + warp;
    if (t >= T_TOK) return;
    const float* xr = x + (size_t)t * H_DIM;

    float acc[N_EXP];
#pragma unroll
    for (int e = 0; e < N_EXP; e++) acc[e] = 0.f;
    for (int i = lane; i < H_DIM; i += 32) {
        float xv = xr[i];
        const float* g = gw + (size_t)i * N_EXP;
#pragma unroll
        for (int e = 0; e < N_EXP; e++) acc[e] += xv * g[e];
    }
#pragma unroll
    for (int off = 16; off > 0; off >>= 1)
#pragma unroll
        for (int e = 0; e < N_EXP; e++) acc[e] += __shfl_xor_sync(0xffffffffu, acc[e], off);

    if (lane == 0) {
        float m = acc[0];
#pragma unroll
        for (int e = 1; e < N_EXP; e++) m = fmaxf(m, acc[e]);
        float p[N_EXP]; float s = 0.f;
#pragma unroll
        for (int e = 0; e < N_EXP; e++) { p[e] = expf(acc[e] - m); s += p[e]; }
        float inv = 1.0f / s;
#pragma unroll
        for (int e = 0; e < N_EXP; e++) p[e] *= inv;

        int e1 = 0; float b1 = p[0];
#pragma unroll
        for (int e = 1; e < N_EXP; e++) if (p[e] > b1) { b1 = p[e]; e1 = e; }
        int e2 = -1; float b2 = -1.f;
#pragma unroll
        for (int e = 0; e < N_EXP; e++) if (e != e1 && p[e] > b2) { b2 = p[e]; e2 = e; }

        float snorm = b1 + b2;
        g_sel[t * 2 + 0] = e1; g_sel[t * 2 + 1] = e2;
        g_wt [t * 2 + 0] = b1 / snorm; g_wt [t * 2 + 1] = b2 / snorm;
        if (logits_out) {
#pragma unroll
            for (int e = 0; e < N_EXP; e++) logits_out[(size_t)t * N_EXP + e] = acc[e];
        }
    }
}

// ---------------- 2. Gather (pad to 128-row blocks) ----------------
__global__ void gather_kernel() {
    const unsigned full = 0xffffffffu;
    int warp = threadIdx.x >> 5;
    int lane = threadIdx.x & 31;
    int e = warp;

    int cnt = 0;
    for (int base = 0; base < T_TOK; base += 32) {
        int t = base + lane;
        bool sel = (g_sel[t * 2] == e) || (g_sel[t * 2 + 1] == e);
        unsigned m = __ballot_sync(full, sel);
        cnt += __popc(m);
    }
    if (lane == 0) g_cnt[e] = cnt;
    __syncthreads();

    if (threadIdx.x == 0) {
        int off = 0;
        for (int ee = 0; ee < N_EXP; ee++) {
            g_off[ee] = off;
            int pad = (g_cnt[ee] + 127) & ~127;
            for (int b = 0; b < pad / 128; b++) g_blk_expert[off / 128 + b] = ee;
            off += pad;
        }
        for (int b = off / 128; b < MAXBLK; b++) g_blk_expert[b] = -1;
        g_total = off;
    }
    __syncthreads();

    int pos = g_off[e];
    for (int base = 0; base < T_TOK; base += 32) {
        int t = base + lane;
        int slot = (g_sel[t * 2] == e) ? 0 : ((g_sel[t * 2 + 1] == e) ? 1 : -1);
        unsigned m = __ballot_sync(full, slot >= 0);
        if (slot >= 0) {
            int idx = pos + __popc(m & ((1u << lane) - 1u));
            g_tok[idx] = t;
            g_rwt[idx] = g_wt[t * 2 + slot];
        }
        pos += __popc(m);
    }
    int c = g_cnt[e];
    int padded = (c + 127) & ~127;
    for (int r = c + lane; r < padded; r += 32) {
        g_tok[g_off[e] + r] = -1;
        g_rwt[g_off[e] + r] = 0.f;
    }
    __syncthreads();
    for (int i = g_total + threadIdx.x; i < MAXROWS; i += 256) { g_tok[i] = -1; g_rwt[i] = 0.f; }
}

// ---------------- 3. Convert gathered x -> bf16 hi/lo ----------------
__device__ __forceinline__ void split2(float a, float b, uint32_t& h, uint32_t& l) {
    __nv_bfloat16 ha = __float2bfloat16(a), hb = __float2bfloat16(b);
    float ra = a - __bfloat162float(ha), rb = b - __bfloat162float(hb);
    __nv_bfloat16 la = __float2bfloat16(ra), lb = __float2bfloat16(rb);
    h = (uint32_t)__bfloat16_as_ushort(ha) | ((uint32_t)__bfloat16_as_ushort(hb) << 16);
    l = (uint32_t)__bfloat16_as_ushort(la) | ((uint32_t)__bfloat16_as_ushort(lb) << 16);
}

__global__ void conv_x_kernel(const float* __restrict__ x) {
    int row = blockIdx.x;
    int t = g_tok[row];
    const float4* src = (t >= 0) ? (const float4*)(x + (size_t)t * H_DIM) : nullptr;
    uint2* dh = (uint2*)(g_a_hi + (size_t)row * H_DIM);
    uint2* dl = (uint2*)(g_a_lo + (size_t)row * H_DIM);
    for (int i = threadIdx.x; i < H_DIM / 4; i += 256) {
        float4 v = src ? src[i] : make_float4(0.f, 0.f, 0.f, 0.f);
        uint2 h, l;
        split2(v.x, v.y, h.x, l.x);
        split2(v.z, v.w, h.y, l.y);
        dh[i] = h; dl[i] = l;
    }
}

// ---------------- 4. Weight transpose + convert: [E][R][C] f32 -> [E][C][R] bf16 hi/lo ----------
template<bool W1>
__global__ void conv_w_kernel(const float* __restrict__ src, int R, int C) {
    __shared__ float tile[32][33];
    int e = blockIdx.z;
    const float* s = src + (size_t)e * R * C;
    __nv_bfloat16* ph = (W1 ? g_w1h : g_w2h) + (size_t)e * R * C;
    __nv_bfloat16* pl = (W1 ? g_w1l : g_w2l) + (size_t)e * R * C;
    int c0 = blockIdx.x * 32, r0 = blockIdx.y * 32;
    int tx = threadIdx.x, ty = threadIdx.y;   // (32, 8)
#pragma unroll
    for (int j = 0; j < 4; j++)
        tile[ty * 4 + j][tx] = s[(size_t)(r0 + ty * 4 + j) * C + c0 + tx];
    __syncthreads();
#pragma unroll
    for (int j = 0; j < 4; j++) {
        float v = tile[tx][ty * 4 + j];
        __nv_bfloat16 h = __float2bfloat16(v);
        __nv_bfloat16 l = __float2bfloat16(v - __bfloat162float(h));
        size_t o = (size_t)(c0 + ty * 4 + j) * R + r0 + tx;
        ph[o] = h; pl[o] = l;
    }
}

// ---------------- 5. split-bf16 GEMM via mma.sync (128x256x32, 3-stage cp.async) ----------------
// Warp tile 64x64 (2x4 warps). G1: D = gelu(A @ w_in^T) -> g_h_hi/lo ;
// !G1: out += rwt * (A @ w_out^T)  (atomic scatter, 2 adds/elem -> deterministic)
template<bool G1>
__global__ void __launch_bounds__(256) gemm_mma(float* __restrict__ outp) {
    constexpr int K    = G1 ? H_DIM : I_DIM;
    constexpr int NTOT = G1 ? I_DIM : H_DIM;
    constexpr int NCH  = K / KCHUNK;

    int e = g_blk_expert[blockIdx.y];
    if (e < 0) return;
    int row0 = blockIdx.y * MTILE;
    int col0 = blockIdx.x * NTILE;

    const __nv_bfloat16* srcs[4];
    srcs[0] = (G1 ? g_a_hi : g_h_hi) + (size_t)row0 * K;
    srcs[1] = (G1 ? g_a_lo : g_h_lo) + (size_t)row0 * K;
    srcs[2] = (G1 ? g_w1h : g_w2h) + ((size_t)e * NTOT + col0) * K;
    srcs[3] = (G1 ? g_w1l : g_w2l) + ((size_t)e * NTOT + col0) * K;

    extern __shared__ char dsm[];
    uint32_t sb0 = smem_u32(dsm);

    int tid  = threadIdx.x;
    int wid  = tid >> 5;
    int lane = tid & 31;
    int warpM = wid >> 2;        // 0..1 -> rows 64*warpM
    int warpN = wid & 3;         // 0..3 -> cols 64*warpN

    float acc[4][8][4];
#pragma unroll
    for (int i = 0; i < 4; i++)
#pragma unroll
        for (int j = 0; j < 8; j++)
#pragma unroll
            for (int q = 0; q < 4; q++) acc[i][j][q] = 0.f;

    // ---- cp.async stage loader: 3072 x 16B per stage, 12 per thread ----
    auto load_stage = [&](int stg, int c) {
        uint32_t sb = sb0 + (uint32_t)stg * STAGEB;
        int k0 = c * KCHUNK;
#pragma unroll
        for (int mat = 0; mat < 2; mat++) {       // A hi/lo: 128 rows
            const __nv_bfloat16* sp = srcs[mat];
#pragma unroll
            for (int j = 0; j < 2; j++) {
                int id = j * 256 + tid;           // 0..511
                int row = id >> 2, c16 = id & 3;
                uint32_t so = sb + mat * AMATB + row * ROWB + c16 * 16;
                CP_ASYNC16(so, sp + (size_t)row * K + k0 + c16 * 8);
            }
        }
#pragma unroll
        for (int mat = 0; mat < 2; mat++) {       // B hi/lo: 256 rows
            const __nv_bfloat16* sp = srcs[2 + mat];
#pragma unroll
            for (int j = 0; j < 4; j++) {
                int id = j * 256 + tid;           // 0..1023
                int row = id >> 2, c16 = id & 3;
                uint32_t so = sb + BBASE + mat * BMATB + row * ROWB + c16 * 16;
                CP_ASYNC16(so, sp + (size_t)row * K + k0 + c16 * 8);
            }
        }
        CP_COMMIT();
    };

    // preload
#pragma unroll
    for (int s = 0; s < STAGES - 1; s++) load_stage(s, s);

    int lr = lane & 15;
    for (int c = 0; c < NCH; c++) {
        if (c + STAGES - 1 < NCH) load_stage((c + STAGES - 1) % STAGES, c + STAGES - 1);
        else CP_COMMIT();                 // keep group count uniform
        CP_WAIT(STAGES - 1);              // stage c resident
        __syncthreads();

        uint32_t sb = sb0 + (uint32_t)(c % STAGES) * STAGEB;
#pragma unroll
        for (int ks = 0; ks < 2; ks++) {
            uint32_t kofs = (uint32_t)(ks * 32 + (lane >> 4) * 16);
            uint32_t ah[4][4], al[4][4];
#pragma unroll
            for (int mi = 0; mi < 4; mi++) {
                uint32_t ra = sb + (uint32_t)((warpM * 64 + mi * 16 + lr) * ROWB) + kofs;
                LDSM4(ah[mi], ra);
                LDSM4(al[mi], ra + AMATB);
            }
#pragma unroll
            for (int nb = 0; nb < 4; nb++) {
                uint32_t rb = sb + BBASE + (uint32_t)((warpN * 64 + nb * 16 + lr) * ROWB) + kofs;
                uint32_t t0[4], t1[4];
                LDSM4(t0, rb);
                LDSM4(t1, rb + BMATB);
                uint32_t bh0[2] = { t0[0], t0[2] }, bh1[2] = { t0[1], t0[3] };
                uint32_t bl0[2] = { t1[0], t1[2] }, bl1[2] = { t1[1], t1[3] };
#pragma unroll
                for (int mi = 0; mi < 4; mi++) {
                    float* d0 = acc[mi][nb * 2];
                    float* d1 = acc[mi][nb * 2 + 1];
                    mma_bf16(d0, ah[mi], bh0);
                    mma_bf16(d0, ah[mi], bl0);
                    mma_bf16(d0, al[mi], bh0);
                    mma_bf16(d1, ah[mi], bh1);
                    mma_bf16(d1, ah[mi], bl1);
                    mma_bf16(d1, al[mi], bh1);
                }
            }
        }
        __syncthreads();
    }

    // ---- epilogue ----
    int r = lane >> 2;
    int cp = (lane & 3) * 2;
    if (G1) {
#pragma unroll
        for (int mi = 0; mi < 4; mi++)
#pragma unroll
            for (int ni = 0; ni < 8; ni++) {
                int row = row0 + warpM * 64 + mi * 16 + r;
                int col = col0 + warpN * 64 + ni * 8 + cp;
                float* d = acc[mi][ni];
                uint32_t h0, l0, h1, l1;
                split2(gelu_exact(d[0]), gelu_exact(d[1]), h0, l0);
                split2(gelu_exact(d[2]), gelu_exact(d[3]), h1, l1);
                *(uint32_t*)(g_h_hi + (size_t)row * I_DIM + col) = h0;
                *(uint32_t*)(g_h_lo + (size_t)row * I_DIM + col) = l0;
                *(uint32_t*)(g_h_hi + (size_t)(row + 8) * I_DIM + col) = h1;
                *(uint32_t*)(g_h_lo + (size_t)(row + 8) * I_DIM + col) = l1;
            }
    } else {
#pragma unroll
        for (int mi = 0; mi < 4; mi++) {
            int row = row0 + warpM * 64 + mi * 16 + r;
            int t0 = g_tok[row];
            int t1 = g_tok[row + 8];
            float w0 = g_rwt[row], w1 = g_rwt[row + 8];
#pragma unroll
            for (int ni = 0; ni < 8; ni++) {
                int col = col0 + warpN * 64 + ni * 8 + cp;
                float* d = acc[mi][ni];
                if (t0 >= 0) {
                    float* op = outp + (size_t)t0 * H_DIM + col;
                    atomicAdd(op,     w0 * d[0]);
                    atomicAdd(op + 1, w0 * d[1]);
                }
                if (t1 >= 0) {
                    float* op = outp + (size_t)t1 * H_DIM + col;
                    atomicAdd(op,     w1 * d[2]);
                    atomicAdd(op + 1, w1 * d[3]);
                }
            }
        }
    }
}

// ---------------- 6. bias add ----------------
__global__ void bias_kernel(float* __restrict__ out, const float* __restrict__ bias) {
    size_t idx = (size_t)blockIdx.x * blockDim.x + threadIdx.x;
    if (idx < (size_t)T_TOK * H_DIM) out[idx] += bias[idx & (H_DIM - 1)];
}

// ---------------- launch ----------------
extern "C" void kernel_launch(void* const* d_in, const int* in_sizes, int n_in,
                              void* d_out, int out_size) {
    const float* x     = (const float*)d_in[0];   // [B,S,H]
    const float* gw    = (const float*)d_in[1];   // [H,E]
    const float* w_in  = (const float*)d_in[2];   // [E,H,I]
    const float* w_out = (const float*)d_in[3];   // [E,I,H]
    const float* bias  = (const float*)d_in[4];   // [H]
    float* out = (float*)d_out;

    cudaFuncSetAttribute((const void*)gemm_mma<true>,
                         cudaFuncAttributeMaxDynamicSharedMemorySize, DSMEM);
    cudaFuncSetAttribute((const void*)gemm_mma<false>,
                         cudaFuncAttributeMaxDynamicSharedMemorySize, DSMEM);

    cudaMemsetAsync(d_out, 0, (size_t)out_size * sizeof(float), 0);

    const int n_out_main = T_TOK * H_DIM;
    const int n_logits   = T_TOK * N_EXP;
    float* logits = (out_size >= n_out_main + n_logits)
                        ? (out + (size_t)out_size - n_logits) : nullptr;

    router_kernel<<<T_TOK / 8, 256>>>(x, gw, logits);
    gather_kernel<<<1, 256>>>();
    conv_x_kernel<<<MAXROWS, 256>>>(x);
    conv_w_kernel<true ><<<dim3(I_DIM / 32, H_DIM / 32, N_EXP), dim3(32, 8)>>>(w_in,  H_DIM, I_DIM);
    conv_w_kernel<false><<<dim3(H_DIM / 32, I_DIM / 32, N_EXP), dim3(32, 8)>>>(w_out, I_DIM, H_DIM);
    gemm_mma<true ><<<dim3(I_DIM / NTILE, MAXBLK), 256, DSMEM>>>(nullptr);
    gemm_mma<false><<<dim3(H_DIM / NTILE, MAXBLK), 256, DSMEM>>>(out);
    bias_kernel<<<(T_TOK * H_DIM + 255) / 256, 256>>>(out, bias);
}

// round 15
// speedup vs baseline: 3.0622x; 1.0018x over previous
#include <cuda_runtime.h>
#include <cuda_bf16.h>
#include <math.h>
#include <stdint.h>

// Problem constants
#define T_TOK 4096
#define H_DIM 2048
#define I_DIM 8192
#define N_EXP 8
#define TOPK  2

#define MTILE   128
#define NTILE   256
#define KCHUNK  32
#define STAGES  3
#define MAXROWS 9216     // 8192 + 8*127 rounded up to 128
#define MAXBLK  72       // MAXROWS / 128

// per-stage smem layout (bytes): Ah | Al | Bh | Bl ; rows are 80B (32 bf16 = 64B + 16B pad)
#define ROWB    80
#define AMATB   (128 * ROWB)       // 10240
#define BMATB   (256 * ROWB)       // 20480
#define BBASE   (2 * AMATB)        // 20480
#define STAGEB  (2 * AMATB + 2 * BMATB)   // 61440
#define DSMEM   (STAGES * STAGEB)         // 184320

// ---------------- scratch (static device globals; no allocations) ----------------
__device__ int   g_sel[T_TOK * TOPK];
__device__ float g_wt [T_TOK * TOPK];
__device__ int   g_cnt[N_EXP];
__device__ int   g_off[N_EXP];
__device__ int   g_total;
__device__ int   g_tok[MAXROWS];
__device__ float g_rwt[MAXROWS];
__device__ int   g_blk_expert[MAXBLK];

// bf16 split operands
__device__ __nv_bfloat16 g_a_hi[(size_t)MAXROWS * H_DIM];
__device__ __nv_bfloat16 g_a_lo[(size_t)MAXROWS * H_DIM];
__device__ __nv_bfloat16 g_h_hi[(size_t)MAXROWS * I_DIM];
__device__ __nv_bfloat16 g_h_lo[(size_t)MAXROWS * I_DIM];
__device__ __nv_bfloat16 g_w1h[(size_t)N_EXP * I_DIM * H_DIM];  // w_in^T  [E][I][H]
__device__ __nv_bfloat16 g_w1l[(size_t)N_EXP * I_DIM * H_DIM];
__device__ __nv_bfloat16 g_w2h[(size_t)N_EXP * H_DIM * I_DIM];  // w_out^T [E][H][I]
__device__ __nv_bfloat16 g_w2l[(size_t)N_EXP * H_DIM * I_DIM];

__device__ __forceinline__ float gelu_exact(float v) {
    return 0.5f * v * (1.0f + erff(v * 0.70710678118654752440f));
}

__device__ __forceinline__ uint32_t smem_u32(const void* p) {
    uint32_t a;
    asm("{ .reg .u64 t; cvta.to.shared.u64 t, %1; cvt.u32.u64 %0, t; }" : "=r"(a) : "l"(p));
    return a;
}

// ---------------- family-portable PTX: cp.async / ldmatrix / mma.sync ----------------
#define CP_ASYNC16(sm, gp) \
    asm volatile("cp.async.cg.shared.global [%0], [%1], 16;" :: "r"(sm), "l"(gp))
#define CP_COMMIT() asm volatile("cp.async.commit_group;" ::: "memory")
#define CP_WAIT(n)  asm volatile("cp.async.wait_group %0;" :: "n"(n) : "memory")

#define LDSM4(r, addr) \
    asm volatile("ldmatrix.sync.aligned.m8n8.x4.shared.b16 {%0,%1,%2,%3}, [%4];" \
        : "=r"((r)[0]), "=r"((r)[1]), "=r"((r)[2]), "=r"((r)[3]) : "r"(addr))

__device__ __forceinline__ void mma_bf16(float* d, const uint32_t* a, const uint32_t* b) {
    asm volatile(
        "mma.sync.aligned.m16n8k16.row.col.f32.bf16.bf16.f32 "
        "{%0,%1,%2,%3}, {%4,%5,%6,%7}, {%8,%9}, {%0,%1,%2,%3};"
        : "+f"(d[0]), "+f"(d[1]), "+f"(d[2]), "+f"(d[3])
        : "r"(a[0]), "r"(a[1]), "r"(a[2]), "r"(a[3]), "r"(b[0]), "r"(b[1]));
}

// ---------------- 1. Router ----------------
__global__ void router_kernel(const float* __restrict__ x,
                              const float* __restrict__ gw,
                              float* __restrict__ logits_out) {
    int warp = threadIdx.x >> 5;
    int lane = threadIdx.x & 31;
    int t = blockIdx.x * 8 + warp;
    if (t >= T_TOK) return;
    const float* xr = x + (size_t)t * H_DIM;

    float acc[N_EXP];
#pragma unroll
    for (int e = 0; e < N_EXP; e++) acc[e] = 0.f;
    for (int i = lane; i < H_DIM; i += 32) {
        float xv = xr[i];
        const float* g = gw + (size_t)i * N_EXP;
#pragma unroll
        for (int e = 0; e < N_EXP; e++) acc[e] += xv * g[e];
    }
#pragma unroll
    for (int off = 16; off > 0; off >>= 1)
#pragma unroll
        for (int e = 0; e < N_EXP; e++) acc[e] += __shfl_xor_sync(0xffffffffu, acc[e], off);

    if (lane == 0) {
        float m = acc[0];
#pragma unroll
        for (int e = 1; e < N_EXP; e++) m = fmaxf(m, acc[e]);
        float p[N_EXP]; float s = 0.f;
#pragma unroll
        for (int e = 0; e < N_EXP; e++) { p[e] = expf(acc[e] - m); s += p[e]; }
        float inv = 1.0f / s;
#pragma unroll
        for (int e = 0; e < N_EXP; e++) p[e] *= inv;

        int e1 = 0; float b1 = p[0];
#pragma unroll
        for (int e = 1; e < N_EXP; e++) if (p[e] > b1) { b1 = p[e]; e1 = e; }
        int e2 = -1; float b2 = -1.f;
#pragma unroll
        for (int e = 0; e < N_EXP; e++) if (e != e1 && p[e] > b2) { b2 = p[e]; e2 = e; }

        float snorm = b1 + b2;
        g_sel[t * 2 + 0] = e1; g_sel[t * 2 + 1] = e2;
        g_wt [t * 2 + 0] = b1 / snorm; g_wt [t * 2 + 1] = b2 / snorm;
        if (logits_out) {
#pragma unroll
            for (int e = 0; e < N_EXP; e++) logits_out[(size_t)t * N_EXP + e] = acc[e];
        }
    }
}

// ---------------- 2. Gather (pad to 128-row blocks) ----------------
__global__ void gather_kernel() {
    const unsigned full = 0xffffffffu;
    int warp = threadIdx.x >> 5;
    int lane = threadIdx.x & 31;
    int e = warp;

    int cnt = 0;
    for (int base = 0; base < T_TOK; base += 32) {
        int t = base + lane;
        bool sel = (g_sel[t * 2] == e) || (g_sel[t * 2 + 1] == e);
        unsigned m = __ballot_sync(full, sel);
        cnt += __popc(m);
    }
    if (lane == 0) g_cnt[e] = cnt;
    __syncthreads();

    if (threadIdx.x == 0) {
        int off = 0;
        for (int ee = 0; ee < N_EXP; ee++) {
            g_off[ee] = off;
            int pad = (g_cnt[ee] + 127) & ~127;
            for (int b = 0; b < pad / 128; b++) g_blk_expert[off / 128 + b] = ee;
            off += pad;
        }
        for (int b = off / 128; b < MAXBLK; b++) g_blk_expert[b] = -1;
        g_total = off;
    }
    __syncthreads();

    int pos = g_off[e];
    for (int base = 0; base < T_TOK; base += 32) {
        int t = base + lane;
        int slot = (g_sel[t * 2] == e) ? 0 : ((g_sel[t * 2 + 1] == e) ? 1 : -1);
        unsigned m = __ballot_sync(full, slot >= 0);
        if (slot >= 0) {
            int idx = pos + __popc(m & ((1u << lane) - 1u));
            g_tok[idx] = t;
            g_rwt[idx] = g_wt[t * 2 + slot];
        }
        pos += __popc(m);
    }
    int c = g_cnt[e];
    int padded = (c + 127) & ~127;
    for (int r = c + lane; r < padded; r += 32) {
        g_tok[g_off[e] + r] = -1;
        g_rwt[g_off[e] + r] = 0.f;
    }
    __syncthreads();
    for (int i = g_total + threadIdx.x; i < MAXROWS; i += 256) { g_tok[i] = -1; g_rwt[i] = 0.f; }
}

// ---------------- 3. Convert gathered x -> bf16 hi/lo ----------------
__device__ __forceinline__ void split2(float a, float b, uint32_t& h, uint32_t& l) {
    __nv_bfloat16 ha = __float2bfloat16(a), hb = __float2bfloat16(b);
    float ra = a - __bfloat162float(ha), rb = b - __bfloat162float(hb);
    __nv_bfloat16 la = __float2bfloat16(ra), lb = __float2bfloat16(rb);
    h = (uint32_t)__bfloat16_as_ushort(ha) | ((uint32_t)__bfloat16_as_ushort(hb) << 16);
    l = (uint32_t)__bfloat16_as_ushort(la) | ((uint32_t)__bfloat16_as_ushort(lb) << 16);
}

__global__ void conv_x_kernel(const float* __restrict__ x) {
    int row = blockIdx.x;
    int t = g_tok[row];
    const float4* src = (t >= 0) ? (const float4*)(x + (size_t)t * H_DIM) : nullptr;
    uint2* dh = (uint2*)(g_a_hi + (size_t)row * H_DIM);
    uint2* dl = (uint2*)(g_a_lo + (size_t)row * H_DIM);
    for (int i = threadIdx.x; i < H_DIM / 4; i += 256) {
        float4 v = src ? src[i] : make_float4(0.f, 0.f, 0.f, 0.f);
        uint2 h, l;
        split2(v.x, v.y, h.x, l.x);
        split2(v.z, v.w, h.y, l.y);
        dh[i] = h; dl[i] = l;
    }
}

// ---------------- 4. Weight transpose + convert: [E][R][C] f32 -> [E][C][R] bf16 hi/lo ----------
template<bool W1>
__global__ void conv_w_kernel(const float* __restrict__ src, int R, int C) {
    __shared__ float tile[32][33];
    int e = blockIdx.z;
    const float* s = src + (size_t)e * R * C;
    __nv_bfloat16* ph = (W1 ? g_w1h : g_w2h) + (size_t)e * R * C;
    __nv_bfloat16* pl = (W1 ? g_w1l : g_w2l) + (size_t)e * R * C;
    int c0 = blockIdx.x * 32, r0 = blockIdx.y * 32;
    int tx = threadIdx.x, ty = threadIdx.y;   // (32, 8)
#pragma unroll
    for (int j = 0; j < 4; j++)
        tile[ty * 4 + j][tx] = s[(size_t)(r0 + ty * 4 + j) * C + c0 + tx];
    __syncthreads();
#pragma unroll
    for (int j = 0; j < 4; j++) {
        float v = tile[tx][ty * 4 + j];
        __nv_bfloat16 h = __float2bfloat16(v);
        __nv_bfloat16 l = __float2bfloat16(v - __bfloat162float(h));
        size_t o = (size_t)(c0 + ty * 4 + j) * R + r0 + tx;
        ph[o] = h; pl[o] = l;
    }
}

// ---------------- 5. split-bf16 GEMM via mma.sync (128x256x32, 3-stage cp.async) ----------------
// Warp tile 64x64 (2x4 warps). MMAs emitted in 3 combo passes (hh, hl, lh) so that
// consecutive HMMAs never share an accumulator (reuse distance = 32 instructions).
template<bool G1>
__global__ void __launch_bounds__(256) gemm_mma(float* __restrict__ outp) {
    constexpr int K    = G1 ? H_DIM : I_DIM;
    constexpr int NTOT = G1 ? I_DIM : H_DIM;
    constexpr int NCH  = K / KCHUNK;

    int e = g_blk_expert[blockIdx.y];
    if (e < 0) return;
    int row0 = blockIdx.y * MTILE;
    int col0 = blockIdx.x * NTILE;

    const __nv_bfloat16* srcs[4];
    srcs[0] = (G1 ? g_a_hi : g_h_hi) + (size_t)row0 * K;
    srcs[1] = (G1 ? g_a_lo : g_h_lo) + (size_t)row0 * K;
    srcs[2] = (G1 ? g_w1h : g_w2h) + ((size_t)e * NTOT + col0) * K;
    srcs[3] = (G1 ? g_w1l : g_w2l) + ((size_t)e * NTOT + col0) * K;

    extern __shared__ char dsm[];
    uint32_t sb0 = smem_u32(dsm);

    int tid  = threadIdx.x;
    int wid  = tid >> 5;
    int lane = tid & 31;
    int warpM = wid >> 2;        // 0..1 -> rows 64*warpM
    int warpN = wid & 3;         // 0..3 -> cols 64*warpN

    float acc[4][8][4];
#pragma unroll
    for (int i = 0; i < 4; i++)
#pragma unroll
        for (int j = 0; j < 8; j++)
#pragma unroll
            for (int q = 0; q < 4; q++) acc[i][j][q] = 0.f;

    // ---- cp.async stage loader: 3072 x 16B per stage, 12 per thread ----
    auto load_stage = [&](int stg, int c) {
        uint32_t sb = sb0 + (uint32_t)stg * STAGEB;
        int k0 = c * KCHUNK;
#pragma unroll
        for (int mat = 0; mat < 2; mat++) {       // A hi/lo: 128 rows
            const __nv_bfloat16* sp = srcs[mat];
#pragma unroll
            for (int j = 0; j < 2; j++) {
                int id = j * 256 + tid;           // 0..511
                int row = id >> 2, c16 = id & 3;
                uint32_t so = sb + mat * AMATB + row * ROWB + c16 * 16;
                CP_ASYNC16(so, sp + (size_t)row * K + k0 + c16 * 8);
            }
        }
#pragma unroll
        for (int mat = 0; mat < 2; mat++) {       // B hi/lo: 256 rows
            const __nv_bfloat16* sp = srcs[2 + mat];
#pragma unroll
            for (int j = 0; j < 4; j++) {
                int id = j * 256 + tid;           // 0..1023
                int row = id >> 2, c16 = id & 3;
                uint32_t so = sb + BBASE + mat * BMATB + row * ROWB + c16 * 16;
                CP_ASYNC16(so, sp + (size_t)row * K + k0 + c16 * 8);
            }
        }
        CP_COMMIT();
    };

    // preload
#pragma unroll
    for (int s = 0; s < STAGES - 1; s++) load_stage(s, s);

    int lr = lane & 15;
    for (int c = 0; c < NCH; c++) {
        if (c + STAGES - 1 < NCH) load_stage((c + STAGES - 1) % STAGES, c + STAGES - 1);
        else CP_COMMIT();                 // keep group count uniform
        CP_WAIT(STAGES - 1);              // stage c resident
        __syncthreads();

        uint32_t sb = sb0 + (uint32_t)(c % STAGES) * STAGEB;
#pragma unroll
        for (int ks = 0; ks < 2; ks++) {
            uint32_t kofs = (uint32_t)(ks * 32 + (lane >> 4) * 16);

            // ---- stage ALL fragments for this k-step ----
            uint32_t ah[4][4], al[4][4], bh[8][2], bl[8][2];
#pragma unroll
            for (int mi = 0; mi < 4; mi++) {
                uint32_t ra = sb + (uint32_t)((warpM * 64 + mi * 16 + lr) * ROWB) + kofs;
                LDSM4(ah[mi], ra);
                LDSM4(al[mi], ra + AMATB);
            }
#pragma unroll
            for (int nb = 0; nb < 4; nb++) {
                uint32_t rb = sb + BBASE + (uint32_t)((warpN * 64 + nb * 16 + lr) * ROWB) + kofs;
                uint32_t t0[4], t1[4];
                LDSM4(t0, rb);
                LDSM4(t1, rb + BMATB);
                bh[nb * 2][0] = t0[0]; bh[nb * 2][1] = t0[2];
                bh[nb * 2 + 1][0] = t0[1]; bh[nb * 2 + 1][1] = t0[3];
                bl[nb * 2][0] = t1[0]; bl[nb * 2][1] = t1[2];
                bl[nb * 2 + 1][0] = t1[1]; bl[nb * 2 + 1][1] = t1[3];
            }

            // ---- pass 1: Ah x Bh (32 independent MMAs) ----
#pragma unroll
            for (int mi = 0; mi < 4; mi++)
#pragma unroll
                for (int ni = 0; ni < 8; ni++)
                    mma_bf16(acc[mi][ni], ah[mi], bh[ni]);
            // ---- pass 2: Ah x Bl ----
#pragma unroll
            for (int mi = 0; mi < 4; mi++)
#pragma unroll
                for (int ni = 0; ni < 8; ni++)
                    mma_bf16(acc[mi][ni], ah[mi], bl[ni]);
            // ---- pass 3: Al x Bh ----
#pragma unroll
            for (int mi = 0; mi < 4; mi++)
#pragma unroll
                for (int ni = 0; ni < 8; ni++)
                    mma_bf16(acc[mi][ni], al[mi], bh[ni]);
        }
        __syncthreads();
    }

    // ---- epilogue ----
    int r = lane >> 2;
    int cp = (lane & 3) * 2;
    if (G1) {
#pragma unroll
        for (int mi = 0; mi < 4; mi++)
#pragma unroll
            for (int ni = 0; ni < 8; ni++) {
                int row = row0 + warpM * 64 + mi * 16 + r;
                int col = col0 + warpN * 64 + ni * 8 + cp;
                float* d = acc[mi][ni];
                uint32_t h0, l0, h1, l1;
                split2(gelu_exact(d[0]), gelu_exact(d[1]), h0, l0);
                split2(gelu_exact(d[2]), gelu_exact(d[3]), h1, l1);
                *(uint32_t*)(g_h_hi + (size_t)row * I_DIM + col) = h0;
                *(uint32_t*)(g_h_lo + (size_t)row * I_DIM + col) = l0;
                *(uint32_t*)(g_h_hi + (size_t)(row + 8) * I_DIM + col) = h1;
                *(uint32_t*)(g_h_lo + (size_t)(row + 8) * I_DIM + col) = l1;
            }
    } else {
#pragma unroll
        for (int mi = 0; mi < 4; mi++) {
            int row = row0 + warpM * 64 + mi * 16 + r;
            int t0 = g_tok[row];
            int t1 = g_tok[row + 8];
            float w0 = g_rwt[row], w1 = g_rwt[row + 8];
#pragma unroll
            for (int ni = 0; ni < 8; ni++) {
                int col = col0 + warpN * 64 + ni * 8 + cp;
                float* d = acc[mi][ni];
                if (t0 >= 0) {
                    float* op = outp + (size_t)t0 * H_DIM + col;
                    atomicAdd(op,     w0 * d[0]);
                    atomicAdd(op + 1, w0 * d[1]);
                }
                if (t1 >= 0) {
                    float* op = outp + (size_t)t1 * H_DIM + col;
                    atomicAdd(op,     w1 * d[2]);
                    atomicAdd(op + 1, w1 * d[3]);
                }
            }
        }
    }
}

// ---------------- 6. bias add ----------------
__global__ void bias_kernel(float* __restrict__ out, const float* __restrict__ bias) {
    size_t idx = (size_t)blockIdx.x * blockDim.x + threadIdx.x;
    if (idx < (size_t)T_TOK * H_DIM) out[idx] += bias[idx & (H_DIM - 1)];
}

// ---------------- launch ----------------
extern "C" void kernel_launch(void* const* d_in, const int* in_sizes, int n_in,
                              void* d_out, int out_size) {
    const float* x     = (const float*)d_in[0];   // [B,S,H]
    const float* gw    = (const float*)d_in[1];   // [H,E]
    const float* w_in  = (const float*)d_in[2];   // [E,H,I]
    const float* w_out = (const float*)d_in[3];   // [E,I,H]
    const float* bias  = (const float*)d_in[4];   // [H]
    float* out = (float*)d_out;

    cudaFuncSetAttribute((const void*)gemm_mma<true>,
                         cudaFuncAttributeMaxDynamicSharedMemorySize, DSMEM);
    cudaFuncSetAttribute((const void*)gemm_mma<false>,
                         cudaFuncAttributeMaxDynamicSharedMemorySize, DSMEM);

    cudaMemsetAsync(d_out, 0, (size_t)out_size * sizeof(float), 0);

    const int n_out_main = T_TOK * H_DIM;
    const int n_logits   = T_TOK * N_EXP;
    float* logits = (out_size >= n_out_main + n_logits)
                        ? (out + (size_t)out_size - n_logits) : nullptr;

    router_kernel<<<T_TOK / 8, 256>>>(x, gw, logits);
    gather_kernel<<<1, 256>>>();
    conv_x_kernel<<<MAXROWS, 256>>>(x);
    conv_w_kernel<true ><<<dim3(I_DIM / 32, H_DIM / 32, N_EXP), dim3(32, 8)>>>(w_in,  H_DIM, I_DIM);
    conv_w_kernel<false><<<dim3(H_DIM / 32, I_DIM / 32, N_EXP), dim3(32, 8)>>>(w_out, I_DIM, H_DIM);
    gemm_mma<true ><<<dim3(I_DIM / NTILE, MAXBLK), 256, DSMEM>>>(nullptr);
    gemm_mma<false><<<dim3(H_DIM / NTILE, MAXBLK), 256, DSMEM>>>(out);
    bias_kernel<<<(T_TOK * H_DIM + 255) / 256, 256>>>(out, bias);
}

// round 16
// speedup vs baseline: 7.0390x; 2.2987x over previous
#include <cuda_runtime.h>
#include <cuda_fp16.h>
#include <math.h>
#include <stdint.h>

// Problem constants
#define T_TOK 4096
#define H_DIM 2048
#define I_DIM 8192
#define N_EXP 8
#define TOPK  2

#define MTILE   128
#define NTILE   256
#define KCHUNK  32
#define STAGES  4
#define MAXROWS 9216     // 8192 + 8*127 rounded up to 128
#define MAXBLK  72       // MAXROWS / 128

// per-stage smem layout (bytes): A | B ; rows are 80B (32 fp16 = 64B + 16B pad)
#define ROWB    80
#define AMATB   (128 * ROWB)       // 10240
#define BMATB   (256 * ROWB)       // 20480
#define STAGEB  (AMATB + BMATB)    // 30720
#define DSMEM   (STAGES * STAGEB)  // 122880

// ---------------- scratch (static device globals; no allocations) ----------------
__device__ int   g_sel[T_TOK * TOPK];
__device__ float g_wt [T_TOK * TOPK];
__device__ int   g_cnt[N_EXP];
__device__ int   g_off[N_EXP];
__device__ int   g_total;
__device__ int   g_tok[MAXROWS];
__device__ float g_rwt[MAXROWS];
__device__ int   g_blk_expert[MAXBLK];

// fp16 operands (single precision pass; e5m10 keeps GEMM rel_err ~3e-4)
__device__ __half g_a [(size_t)MAXROWS * H_DIM];
__device__ __half g_h [(size_t)MAXROWS * I_DIM];
__device__ __half g_w1[(size_t)N_EXP * I_DIM * H_DIM];  // w_in^T  [E][I][H]
__device__ __half g_w2[(size_t)N_EXP * H_DIM * I_DIM];  // w_out^T [E][H][I]

__device__ __forceinline__ float gelu_exact(float v) {
    return 0.5f * v * (1.0f + erff(v * 0.70710678118654752440f));
}

__device__ __forceinline__ uint32_t smem_u32(const void* p) {
    uint32_t a;
    asm("{ .reg .u64 t; cvta.to.shared.u64 t, %1; cvt.u32.u64 %0, t; }" : "=r"(a) : "l"(p));
    return a;
}

// ---------------- family-portable PTX: cp.async / ldmatrix / mma.sync ----------------
#define CP_ASYNC16(sm, gp) \
    asm volatile("cp.async.cg.shared.global [%0], [%1], 16;" :: "r"(sm), "l"(gp))
#define CP_COMMIT() asm volatile("cp.async.commit_group;" ::: "memory")
#define CP_WAIT(n)  asm volatile("cp.async.wait_group %0;" :: "n"(n) : "memory")

#define LDSM4(r, addr) \
    asm volatile("ldmatrix.sync.aligned.m8n8.x4.shared.b16 {%0,%1,%2,%3}, [%4];" \
        : "=r"((r)[0]), "=r"((r)[1]), "=r"((r)[2]), "=r"((r)[3]) : "r"(addr))

__device__ __forceinline__ void mma_fp16(float* d, const uint32_t* a, const uint32_t* b) {
    asm volatile(
        "mma.sync.aligned.m16n8k16.row.col.f32.f16.f16.f32 "
        "{%0,%1,%2,%3}, {%4,%5,%6,%7}, {%8,%9}, {%0,%1,%2,%3};"
        : "+f"(d[0]), "+f"(d[1]), "+f"(d[2]), "+f"(d[3])
        : "r"(a[0]), "r"(a[1]), "r"(a[2]), "r"(a[3]), "r"(b[0]), "r"(b[1]));
}

// ---------------- 1. Router (exact fp32; logits are a checked output) ----------------
__global__ void router_kernel(const float* __restrict__ x,
                              const float* __restrict__ gw,
                              float* __restrict__ logits_out) {
    int warp = threadIdx.x >> 5;
    int lane = threadIdx.x & 31;
    int t = blockIdx.x * 8 + warp;
    if (t >= T_TOK) return;
    const float* xr = x + (size_t)t * H_DIM;

    float acc[N_EXP];
#pragma unroll
    for (int e = 0; e < N_EXP; e++) acc[e] = 0.f;
    for (int i = lane; i < H_DIM; i += 32) {
        float xv = xr[i];
        const float* g = gw + (size_t)i * N_EXP;
#pragma unroll
        for (int e = 0; e < N_EXP; e++) acc[e] += xv * g[e];
    }
#pragma unroll
    for (int off = 16; off > 0; off >>= 1)
#pragma unroll
        for (int e = 0; e < N_EXP; e++) acc[e] += __shfl_xor_sync(0xffffffffu, acc[e], off);

    if (lane == 0) {
        float m = acc[0];
#pragma unroll
        for (int e = 1; e < N_EXP; e++) m = fmaxf(m, acc[e]);
        float p[N_EXP]; float s = 0.f;
#pragma unroll
        for (int e = 0; e < N_EXP; e++) { p[e] = expf(acc[e] - m); s += p[e]; }
        float inv = 1.0f / s;
#pragma unroll
        for (int e = 0; e < N_EXP; e++) p[e] *= inv;

        int e1 = 0; float b1 = p[0];
#pragma unroll
        for (int e = 1; e < N_EXP; e++) if (p[e] > b1) { b1 = p[e]; e1 = e; }
        int e2 = -1; float b2 = -1.f;
#pragma unroll
        for (int e = 0; e < N_EXP; e++) if (e != e1 && p[e] > b2) { b2 = p[e]; e2 = e; }

        float snorm = b1 + b2;
        g_sel[t * 2 + 0] = e1; g_sel[t * 2 + 1] = e2;
        g_wt [t * 2 + 0] = b1 / snorm; g_wt [t * 2 + 1] = b2 / snorm;
        if (logits_out) {
#pragma unroll
            for (int e = 0; e < N_EXP; e++) logits_out[(size_t)t * N_EXP + e] = acc[e];
        }
    }
}

// ---------------- 2. Gather (pad to 128-row blocks) ----------------
__global__ void gather_kernel() {
    const unsigned full = 0xffffffffu;
    int warp = threadIdx.x >> 5;
    int lane = threadIdx.x & 31;
    int e = warp;

    int cnt = 0;
    for (int base = 0; base < T_TOK; base += 32) {
        int t = base + lane;
        bool sel = (g_sel[t * 2] == e) || (g_sel[t * 2 + 1] == e);
        unsigned m = __ballot_sync(full, sel);
        cnt += __popc(m);
    }
    if (lane == 0) g_cnt[e] = cnt;
    __syncthreads();

    if (threadIdx.x == 0) {
        int off = 0;
        for (int ee = 0; ee < N_EXP; ee++) {
            g_off[ee] = off;
            int pad = (g_cnt[ee] + 127) & ~127;
            for (int b = 0; b < pad / 128; b++) g_blk_expert[off / 128 + b] = ee;
            off += pad;
        }
        for (int b = off / 128; b < MAXBLK; b++) g_blk_expert[b] = -1;
        g_total = off;
    }
    __syncthreads();

    int pos = g_off[e];
    for (int base = 0; base < T_TOK; base += 32) {
        int t = base + lane;
        int slot = (g_sel[t * 2] == e) ? 0 : ((g_sel[t * 2 + 1] == e) ? 1 : -1);
        unsigned m = __ballot_sync(full, slot >= 0);
        if (slot >= 0) {
            int idx = pos + __popc(m & ((1u << lane) - 1u));
            g_tok[idx] = t;
            g_rwt[idx] = g_wt[t * 2 + slot];
        }
        pos += __popc(m);
    }
    int c = g_cnt[e];
    int padded = (c + 127) & ~127;
    for (int r = c + lane; r < padded; r += 32) {
        g_tok[g_off[e] + r] = -1;
        g_rwt[g_off[e] + r] = 0.f;
    }
    __syncthreads();
    for (int i = g_total + threadIdx.x; i < MAXROWS; i += 256) { g_tok[i] = -1; g_rwt[i] = 0.f; }
}

// ---------------- 3. Convert gathered x -> fp16 ----------------
__global__ void conv_x_kernel(const float* __restrict__ x) {
    int row = blockIdx.x;
    int t = g_tok[row];
    const float4* src = (t >= 0) ? (const float4*)(x + (size_t)t * H_DIM) : nullptr;
    uint2* d = (uint2*)(g_a + (size_t)row * H_DIM);
    for (int i = threadIdx.x; i < H_DIM / 4; i += 256) {
        float4 v = src ? src[i] : make_float4(0.f, 0.f, 0.f, 0.f);
        __half2 p0 = __floats2half2_rn(v.x, v.y);
        __half2 p1 = __floats2half2_rn(v.z, v.w);
        uint2 o;
        o.x = *(uint32_t*)&p0;
        o.y = *(uint32_t*)&p1;
        d[i] = o;
    }
}

// ---------------- 4. Weight transpose + convert: [E][R][C] f32 -> [E][C][R] fp16 ----------
template<bool W1>
__global__ void conv_w_kernel(const float* __restrict__ src, int R, int C) {
    __shared__ float tile[32][33];
    int e = blockIdx.z;
    const float* s = src + (size_t)e * R * C;
    __half* p = (W1 ? g_w1 : g_w2) + (size_t)e * R * C;
    int c0 = blockIdx.x * 32, r0 = blockIdx.y * 32;
    int tx = threadIdx.x, ty = threadIdx.y;   // (32, 8)
#pragma unroll
    for (int j = 0; j < 4; j++)
        tile[ty * 4 + j][tx] = s[(size_t)(r0 + ty * 4 + j) * C + c0 + tx];
    __syncthreads();
#pragma unroll
    for (int j = 0; j < 4; j++) {
        float v = tile[tx][ty * 4 + j];
        p[(size_t)(c0 + ty * 4 + j) * R + r0 + tx] = __float2half_rn(v);
    }
}

// ---------------- 5. fp16 GEMM via mma.sync (128x256x32, 4-stage cp.async) ----------------
// Warp tile 64x64 (2x4 warps). G1: D = gelu(A @ w_in^T) -> g_h ;
// !G1: out += rwt * (A @ w_out^T)  (atomic scatter, 2 adds/elem -> deterministic)
template<bool G1>
__global__ void __launch_bounds__(256) gemm_mma(float* __restrict__ outp) {
    constexpr int K    = G1 ? H_DIM : I_DIM;
    constexpr int NTOT = G1 ? I_DIM : H_DIM;
    constexpr int NCH  = K / KCHUNK;

    int e = g_blk_expert[blockIdx.y];
    if (e < 0) return;
    int row0 = blockIdx.y * MTILE;
    int col0 = blockIdx.x * NTILE;

    const __half* Asrc = (G1 ? g_a : g_h) + (size_t)row0 * K;
    const __half* Bsrc = (G1 ? g_w1 : g_w2) + ((size_t)e * NTOT + col0) * K;

    extern __shared__ char dsm[];
    uint32_t sb0 = smem_u32(dsm);

    int tid  = threadIdx.x;
    int lane = tid & 31;
    int wid  = tid >> 5;
    int warpM = wid >> 2;        // 0..1 -> rows 64*warpM
    int warpN = wid & 3;         // 0..3 -> cols 64*warpN

    float acc[4][8][4];
#pragma unroll
    for (int i = 0; i < 4; i++)
#pragma unroll
        for (int j = 0; j < 8; j++)
#pragma unroll
            for (int q = 0; q < 4; q++) acc[i][j][q] = 0.f;

    // ---- cp.async stage loader: 1536 x 16B per stage, 6 per thread ----
    auto load_stage = [&](int stg, int c) {
        uint32_t sb = sb0 + (uint32_t)stg * STAGEB;
        int k0 = c * KCHUNK;
        // A: 128 rows x 32 fp16
#pragma unroll
        for (int j = 0; j < 2; j++) {
            int id = j * 256 + tid;           // 0..511
            int row = id >> 2, c16 = id & 3;
            uint32_t so = sb + row * ROWB + c16 * 16;
            CP_ASYNC16(so, Asrc + (size_t)row * K + k0 + c16 * 8);
        }
        // B: 256 rows x 32 fp16
#pragma unroll
        for (int j = 0; j < 4; j++) {
            int id = j * 256 + tid;           // 0..1023
            int row = id >> 2, c16 = id & 3;
            uint32_t so = sb + AMATB + row * ROWB + c16 * 16;
            CP_ASYNC16(so, Bsrc + (size_t)row * K + k0 + c16 * 8);
        }
        CP_COMMIT();
    };

    // preload
#pragma unroll
    for (int s = 0; s < STAGES - 1; s++) load_stage(s, s);

    int lr = lane & 15;
    for (int c = 0; c < NCH; c++) {
        if (c + STAGES - 1 < NCH) load_stage((c + STAGES - 1) % STAGES, c + STAGES - 1);
        else CP_COMMIT();                 // keep group count uniform
        CP_WAIT(STAGES - 1);              // stage c resident
        __syncthreads();

        uint32_t sb = sb0 + (uint32_t)(c % STAGES) * STAGEB;
#pragma unroll
        for (int ks = 0; ks < 2; ks++) {
            uint32_t kofs = (uint32_t)(ks * 32 + (lane >> 4) * 16);

            uint32_t a[4][4], b[8][2];
#pragma unroll
            for (int mi = 0; mi < 4; mi++) {
                uint32_t ra = sb + (uint32_t)((warpM * 64 + mi * 16 + lr) * ROWB) + kofs;
                LDSM4(a[mi], ra);
            }
#pragma unroll
            for (int nb = 0; nb < 4; nb++) {
                uint32_t rb = sb + AMATB + (uint32_t)((warpN * 64 + nb * 16 + lr) * ROWB) + kofs;
                uint32_t t0[4];
                LDSM4(t0, rb);
                b[nb * 2][0] = t0[0]; b[nb * 2][1] = t0[2];
                b[nb * 2 + 1][0] = t0[1]; b[nb * 2 + 1][1] = t0[3];
            }
#pragma unroll
            for (int mi = 0; mi < 4; mi++)
#pragma unroll
                for (int ni = 0; ni < 8; ni++)
                    mma_fp16(acc[mi][ni], a[mi], b[ni]);
        }
        __syncthreads();
    }

    // ---- epilogue ----
    int r = lane >> 2;
    int cp = (lane & 3) * 2;
    if (G1) {
#pragma unroll
        for (int mi = 0; mi < 4; mi++)
#pragma unroll
            for (int ni = 0; ni < 8; ni++) {
                int row = row0 + warpM * 64 + mi * 16 + r;
                int col = col0 + warpN * 64 + ni * 8 + cp;
                float* d = acc[mi][ni];
                __half2 p0 = __floats2half2_rn(gelu_exact(d[0]), gelu_exact(d[1]));
                __half2 p1 = __floats2half2_rn(gelu_exact(d[2]), gelu_exact(d[3]));
                *(uint32_t*)(g_h + (size_t)row * I_DIM + col)       = *(uint32_t*)&p0;
                *(uint32_t*)(g_h + (size_t)(row + 8) * I_DIM + col) = *(uint32_t*)&p1;
            }
    } else {
#pragma unroll
        for (int mi = 0; mi < 4; mi++) {
            int row = row0 + warpM * 64 + mi * 16 + r;
            int t0 = g_tok[row];
            int t1 = g_tok[row + 8];
            float w0 = g_rwt[row], w1 = g_rwt[row + 8];
#pragma unroll
            for (int ni = 0; ni < 8; ni++) {
                int col = col0 + warpN * 64 + ni * 8 + cp;
                float* d = acc[mi][ni];
                if (t0 >= 0) {
                    float* op = outp + (size_t)t0 * H_DIM + col;
                    atomicAdd(op,     w0 * d[0]);
                    atomicAdd(op + 1, w0 * d[1]);
                }
                if (t1 >= 0) {
                    float* op = outp + (size_t)t1 * H_DIM + col;
                    atomicAdd(op,     w1 * d[2]);
                    atomicAdd(op + 1, w1 * d[3]);
                }
            }
        }
    }
}

// ---------------- 6. bias add ----------------
__global__ void bias_kernel(float* __restrict__ out, const float* __restrict__ bias) {
    size_t idx = (size_t)blockIdx.x * blockDim.x + threadIdx.x;
    if (idx < (size_t)T_TOK * H_DIM) out[idx] += bias[idx & (H_DIM - 1)];
}

// ---------------- launch ----------------
extern "C" void kernel_launch(void* const* d_in, const int* in_sizes, int n_in,
                              void* d_out, int out_size) {
    const float* x     = (const float*)d_in[0];   // [B,S,H]
    const float* gw    = (const float*)d_in[1];   // [H,E]
    const float* w_in  = (const float*)d_in[2];   // [E,H,I]
    const float* w_out = (const float*)d_in[3];   // [E,I,H]
    const float* bias  = (const float*)d_in[4];   // [H]
    float* out = (float*)d_out;

    cudaFuncSetAttribute((const void*)gemm_mma<true>,
                         cudaFuncAttributeMaxDynamicSharedMemorySize, DSMEM);
    cudaFuncSetAttribute((const void*)gemm_mma<false>,
                         cudaFuncAttributeMaxDynamicSharedMemorySize, DSMEM);

    cudaMemsetAsync(d_out, 0, (size_t)out_size * sizeof(float), 0);

    const int n_out_main = T_TOK * H_DIM;
    const int n_logits   = T_TOK * N_EXP;
    float* logits = (out_size >= n_out_main + n_logits)
                        ? (out + (size_t)out_size - n_logits) : nullptr;

    router_kernel<<<T_TOK / 8, 256>>>(x, gw, logits);
    gather_kernel<<<1, 256>>>();
    conv_x_kernel<<<MAXROWS, 256>>>(x);
    conv_w_kernel<true ><<<dim3(I_DIM / 32, H_DIM / 32, N_EXP), dim3(32, 8)>>>(w_in,  H_DIM, I_DIM);
    conv_w_kernel<false><<<dim3(H_DIM / 32, I_DIM / 32, N_EXP), dim3(32, 8)>>>(w_out, I_DIM, H_DIM);
    gemm_mma<true ><<<dim3(I_DIM / NTILE, MAXBLK), 256, DSMEM>>>(nullptr);
    gemm_mma<false><<<dim3(H_DIM / NTILE, MAXBLK), 256, DSMEM>>>(out);
    bias_kernel<<<(T_TOK * H_DIM + 255) / 256, 256>>>(out, bias);
}